// round 4
// baseline (speedup 1.0000x reference)
#include <cuda_runtime.h>
#include <math.h>

#define N    4096
#define KK   50
#define LW   64
#define NG   (LW*LW)

// spatial grid
#define GC    40                 // cells per dim
#define NC    (GC*GC*GC)         // 64000
#define GLO   (-6.5f)
#define GINV  (GC / 13.0f)       // 1/cell
#define CAP   1024               // per-warp candidate list capacity

// ---------------- scratch (device globals; no allocation allowed) -------------
__device__ float  g_d2[N];
__device__ int    g_idx[N*KK];
__device__ float  g_nrm[N*3];
__device__ float  g_t1[N*3];
__device__ float  g_t2[N*3];
__device__ float  g_dt[N*KK*2];
__device__ float  g_coords[N*KK*2];
__device__ float  g_maxlen[N];
__device__ int    g_counts[N];
__device__ float  g_gauss[N];
// grid structures
__device__ int    g_cnt[NC];
__device__ int    g_fill[NC];
__device__ int    g_start[NC+1];
__device__ int    g_cellOf[N];
__device__ float4 g_p4[N];
__device__ int    g_sidx[N];

__device__ __forceinline__ int clampi(int v, int lo, int hi) {
    return v < lo ? lo : (v > hi ? hi : v);
}

// ---------------- grid build --------------------------------------------------
__global__ void zero_kernel() {
    int i = blockIdx.x * blockDim.x + threadIdx.x;
    if (i < NC) { g_cnt[i] = 0; g_fill[i] = 0; }
}

__global__ void assign_kernel(const float* __restrict__ pts) {
    int i = blockIdx.x * blockDim.x + threadIdx.x;
    if (i >= N) return;
    float x = pts[3*i+0], y = pts[3*i+1], z = pts[3*i+2];
    g_d2[i] = (x*x + y*y) + z*z;               // EXACT same expression as before
    int cx = clampi((int)floorf((x - GLO) * GINV), 0, GC-1);
    int cy = clampi((int)floorf((y - GLO) * GINV), 0, GC-1);
    int cz = clampi((int)floorf((z - GLO) * GINV), 0, GC-1);
    int c = (cx*GC + cy)*GC + cz;
    g_cellOf[i] = c;
    atomicAdd(&g_cnt[c], 1);
}

__global__ void prefix_kernel() {
    __shared__ int pa[1024], pb[1024];
    int t = threadIdx.x;
    const int CH = 63;                          // 1024*63 = 64512 >= NC
    int base = t * CH;
    int s = 0;
    for (int k = 0; k < CH; k++) { int c = base + k; if (c < NC) s += g_cnt[c]; }
    pa[t] = s;
    __syncthreads();
    int* src = pa; int* dst = pb;
    for (int off = 1; off < 1024; off <<= 1) {
        int v = src[t];
        if (t >= off) v += src[t - off];
        dst[t] = v;
        __syncthreads();
        int* tmp = src; src = dst; dst = tmp;
    }
    int run = src[t] - s;                       // exclusive prefix
    for (int k = 0; k < CH; k++) {
        int c = base + k;
        if (c < NC) { g_start[c] = run; run += g_cnt[c]; }
    }
    if (t == 1023) g_start[NC] = run;
}

__global__ void scatter_kernel(const float* __restrict__ pts) {
    int i = blockIdx.x * blockDim.x + threadIdx.x;
    if (i >= N) return;
    int c = g_cellOf[i];
    int slot = g_start[c] + atomicAdd(&g_fill[c], 1);
    g_p4[slot] = make_float4(pts[3*i+0], pts[3*i+1], pts[3*i+2], g_d2[i]);
    g_sidx[slot] = i;
}

// ---------------- grid KNN: one warp per query --------------------------------
// Exact top-50 by (dist_key, idx): distances use the bit-identical formula of
// the previously passing brute-force kernel, and the candidate set is a
// guaranteed superset of the true top-50, so g_idx is bit-identical.
__global__ __launch_bounds__(128) void knn_grid_kernel(const float* __restrict__ pts) {
    __shared__ unsigned long long lists[4][CAP];
    int wid  = threadIdx.x >> 5;
    int lane = threadIdx.x & 31;
    int q = blockIdx.x * 4 + wid;
    if (q >= N) return;
    unsigned long long* list = lists[wid];

    float qx = pts[3*q+0], qy = pts[3*q+1], qz = pts[3*q+2];
    float d2i = g_d2[q];
    int qcx = clampi((int)floorf((qx - GLO) * GINV), 0, GC-1);
    int qcy = clampi((int)floorf((qy - GLO) * GINV), 0, GC-1);
    int qcz = clampi((int)floorf((qz - GLO) * GINV), 0, GC-1);

    // --- step 1: smallest cube (Chebyshev radius L) holding >= 50 points ------
    int lox=qcx, hix=qcx, loy=qcy, hiy=qcy, loz=qcz, hiz=qcz;
    for (int L = 0; L < GC; L++) {
        lox = qcx-L < 0 ? 0 : qcx-L;  hix = qcx+L > GC-1 ? GC-1 : qcx+L;
        loy = qcy-L < 0 ? 0 : qcy-L;  hiy = qcy+L > GC-1 ? GC-1 : qcy+L;
        loz = qcz-L < 0 ? 0 : qcz-L;  hiz = qcz+L > GC-1 ? GC-1 : qcz+L;
        int nx = hix-lox+1, ny = hiy-loy+1, nz = hiz-loz+1;
        int tot = nx*ny*nz;
        int s = 0;
        for (int u = lane; u < tot; u += 32) {
            int ux = u / (ny*nz); int rem = u - ux*(ny*nz);
            int uy = rem / nz;    int uz = rem - uy*nz;
            s += g_cnt[((lox+ux)*GC + (loy+uy))*GC + (loz+uz)];
        }
        #pragma unroll
        for (int o = 16; o; o >>= 1) s += __shfl_xor_sync(0xffffffffu, s, o);
        if (s >= KK) break;
    }

    // --- step 2: gather cube points, find 50th-best key (upper bound) ---------
    int wc = 0;
    for (int ax = lox; ax <= hix; ax++)
    for (int ay = loy; ay <= hiy; ay++) {
        int rowb = (ax*GC + ay)*GC;
        for (int az = loz; az <= hiz; az++) {
            int cell = rowb + az;
            int s0 = g_start[cell], s1 = g_start[cell+1];
            for (int b = s0; b < s1; b += 32) {
                int p = b + lane;
                bool act = p < s1;
                unsigned long long pk = 0xFFFFFFFFFFFFFFFFull;
                if (act) {
                    float4 P = g_p4[p];
                    int pj = g_sidx[p];
                    float dot = (qx*P.x + qy*P.y) + qz*P.z;
                    float sd  = (d2i - 2.0f*dot) + P.w;     // EXACT formula
                    unsigned key = __float_as_uint(sd);
                    pk = ((unsigned long long)key << 32) | (unsigned)pj;
                }
                unsigned m = __ballot_sync(0xffffffffu, act);
                int off = __popc(m & ((1u << lane) - 1u));
                int slot = wc + off;
                if (act && slot < CAP) list[slot] = pk;
                wc += __popc(m);
            }
        }
    }
    int M = wc < CAP ? wc : CAP;
    __syncwarp();

    unsigned key50 = 0;
    for (int r = 0; r < KK; r++) {
        unsigned long long best = 0xFFFFFFFFFFFFFFFFull; int bslot = 0;
        for (int s2 = lane; s2 < M; s2 += 32) {
            unsigned long long v = list[s2];
            if (v < best) { best = v; bslot = s2; }
        }
        #pragma unroll
        for (int o = 16; o; o >>= 1) {
            unsigned long long ov = __shfl_down_sync(0xffffffffu, best, o);
            int os = __shfl_down_sync(0xffffffffu, bslot, o);
            if (ov < best) { best = ov; bslot = os; }
        }
        best  = __shfl_sync(0xffffffffu, best, 0);
        bslot = __shfl_sync(0xffffffffu, bslot, 0);
        if (lane == 0) list[bslot] = 0xFFFFFFFFFFFFFFFFull;
        if (r == KK-1) key50 = (unsigned)(best >> 32);
        __syncwarp();
    }

    // --- step 3: rescan sphere-covering cube with key filter, exact extract ---
    float f50 = __uint_as_float(key50);
    f50 = fmaxf(f50, 0.0f);
    float rr = sqrtf(f50) * 1.0005f + 1e-6f;
    lox = clampi((int)floorf((qx - rr - GLO) * GINV), 0, GC-1);
    hix = clampi((int)floorf((qx + rr - GLO) * GINV), 0, GC-1);
    loy = clampi((int)floorf((qy - rr - GLO) * GINV), 0, GC-1);
    hiy = clampi((int)floorf((qy + rr - GLO) * GINV), 0, GC-1);
    loz = clampi((int)floorf((qz - rr - GLO) * GINV), 0, GC-1);
    hiz = clampi((int)floorf((qz + rr - GLO) * GINV), 0, GC-1);

    wc = 0;
    for (int ax = lox; ax <= hix; ax++)
    for (int ay = loy; ay <= hiy; ay++) {
        int rowb = (ax*GC + ay)*GC;
        for (int az = loz; az <= hiz; az++) {
            int cell = rowb + az;
            int s0 = g_start[cell], s1 = g_start[cell+1];
            for (int b = s0; b < s1; b += 32) {
                int p = b + lane;
                bool act = p < s1;
                bool keep = false;
                unsigned long long pk = 0xFFFFFFFFFFFFFFFFull;
                if (act) {
                    float4 P = g_p4[p];
                    int pj = g_sidx[p];
                    float dot = (qx*P.x + qy*P.y) + qz*P.z;
                    float sd  = (d2i - 2.0f*dot) + P.w;     // EXACT formula
                    unsigned key = __float_as_uint(sd);
                    if (key <= key50) {
                        keep = true;
                        pk = ((unsigned long long)key << 32) | (unsigned)pj;
                    }
                }
                unsigned m = __ballot_sync(0xffffffffu, keep);
                int off = __popc(m & ((1u << lane) - 1u));
                int slot = wc + off;
                if (keep && slot < CAP) list[slot] = pk;
                wc += __popc(m);
            }
        }
    }
    M = wc < CAP ? wc : CAP;
    __syncwarp();

    for (int r = 0; r < KK; r++) {
        unsigned long long best = 0xFFFFFFFFFFFFFFFFull; int bslot = 0;
        for (int s2 = lane; s2 < M; s2 += 32) {
            unsigned long long v = list[s2];
            if (v < best) { best = v; bslot = s2; }
        }
        #pragma unroll
        for (int o = 16; o; o >>= 1) {
            unsigned long long ov = __shfl_down_sync(0xffffffffu, best, o);
            int os = __shfl_down_sync(0xffffffffu, bslot, o);
            if (ov < best) { best = ov; bslot = os; }
        }
        best  = __shfl_sync(0xffffffffu, best, 0);
        bslot = __shfl_sync(0xffffffffu, bslot, 0);
        if (lane == 0) {
            list[bslot] = 0xFFFFFFFFFFFFFFFFull;
            g_idx[q*KK + r] = (int)(unsigned)(best & 0xFFFFFFFFu);
        }
        __syncwarp();
    }
}

// =============== faithful fp32 LAPACK ports (ssyevd path for n=3) =============
__device__ __forceinline__ float slapy2f(float x, float y) {
    float xa = fabsf(x), ya = fabsf(y);
    float w = fmaxf(xa, ya), zz = fminf(xa, ya);
    if (zz == 0.0f) return w;
    float q = zz / w;
    return w * sqrtf(1.0f + q*q);
}

__device__ __forceinline__ void slartgf(float f, float g, float* c, float* s, float* r) {
    if (g == 0.0f)      { *c = 1.0f; *s = 0.0f; *r = f; }
    else if (f == 0.0f) { *c = 0.0f; *s = copysignf(1.0f, g); *r = fabsf(g); }
    else {
        float d = sqrtf(f*f + g*g);
        *c = fabsf(f) / d;
        *r = copysignf(d, f);
        *s = g / (*r);
    }
}

__device__ void slaev2f(float a, float b, float c,
                        float* rt1, float* rt2, float* cs1, float* sn1) {
    float sm  = a + c;
    float df  = a - c;
    float adf = fabsf(df);
    float tb  = b + b;
    float ab  = fabsf(tb);
    float acmx, acmn;
    if (fabsf(a) > fabsf(c)) { acmx = a; acmn = c; }
    else                     { acmx = c; acmn = a; }
    float rt;
    if (adf > ab)      rt = adf * sqrtf(1.0f + (ab/adf)*(ab/adf));
    else if (adf < ab) rt = ab  * sqrtf(1.0f + (adf/ab)*(adf/ab));
    else               rt = ab  * sqrtf(2.0f);
    int sgn1;
    if (sm < 0.0f) {
        *rt1 = 0.5f*(sm - rt); sgn1 = -1;
        *rt2 = (acmx / *rt1)*acmn - (b / *rt1)*b;
    } else if (sm > 0.0f) {
        *rt1 = 0.5f*(sm + rt); sgn1 = 1;
        *rt2 = (acmx / *rt1)*acmn - (b / *rt1)*b;
    } else {
        *rt1 = 0.5f*rt; *rt2 = -0.5f*rt; sgn1 = 1;
    }
    int sgn2;
    float cs;
    if (df >= 0.0f) { cs = df + rt; sgn2 = 1; }
    else            { cs = df - rt; sgn2 = -1; }
    float acs = fabsf(cs);
    if (acs > ab) {
        float ct = -tb / cs;
        *sn1 = 1.0f / sqrtf(1.0f + ct*ct);
        *cs1 = ct * (*sn1);
    } else {
        if (ab == 0.0f) { *cs1 = 1.0f; *sn1 = 0.0f; }
        else {
            float tn = -cs / tb;
            *cs1 = 1.0f / sqrtf(1.0f + tn*tn);
            *sn1 = tn * (*cs1);
        }
    }
    if (sgn1 == sgn2) { float tn = *cs1; *cs1 = -(*sn1); *sn1 = tn; }
}

__device__ void ssteqr3(float* d, float* e, float z[3][3]) {
    const float eps    = 5.9604645e-08f;
    const float eps2   = eps * eps;
    const float safmin = 1.1754944e-38f;
    const int   n = 3;
    const int   nmaxit = n * 30;
    int jtot = 0;
    int l1 = 0, l, m, lsv, lend, lendsv;
    float p, g, r, c, s, f, b, rt1, rt2;

L10:
    if (l1 > n-1) goto L160;
    if (l1 > 0) e[l1-1] = 0.0f;
    for (m = l1; m <= n-2; m++) {
        float tst = fabsf(e[m]);
        if (tst == 0.0f) goto L30;
        if (tst <= (sqrtf(fabsf(d[m])) * sqrtf(fabsf(d[m+1]))) * eps) {
            e[m] = 0.0f; goto L30;
        }
    }
    m = n-1;
L30:
    l = l1; lsv = l; lend = m; lendsv = lend; l1 = m + 1;
    if (lend == l) goto L10;
    {
        float anorm = 0.0f;
        for (int i = l; i <= lend; i++)   anorm = fmaxf(anorm, fabsf(d[i]));
        for (int i = l; i <= lend-1; i++) anorm = fmaxf(anorm, fabsf(e[i]));
        if (anorm == 0.0f) goto L10;
    }
    if (fabsf(d[lend]) < fabsf(d[l])) { lend = lsv; l = lendsv; }
    if (lend > l) {
L40:
        if (l != lend) {
            for (m = l; m <= lend-1; m++) {
                float tst = e[m]*e[m];
                if (tst <= (eps2*fabsf(d[m]))*fabsf(d[m+1]) + safmin) goto L60;
            }
        }
        m = lend;
L60:
        if (m < lend) e[m] = 0.0f;
        p = d[l];
        if (m == l) goto L80;
        if (m == l+1) {
            slaev2f(d[l], e[l], d[l+1], &rt1, &rt2, &c, &s);
            for (int i = 0; i < 3; i++) {
                float tt = z[i][l+1];
                z[i][l+1] = c*tt - s*z[i][l];
                z[i][l]   = s*tt + c*z[i][l];
            }
            d[l] = rt1; d[l+1] = rt2; e[l] = 0.0f;
            l += 2;
            if (l <= lend) goto L40;
            goto L140;
        }
        if (jtot == nmaxit) goto L140;
        jtot++;
        g = (d[l+1] - p) / (2.0f * e[l]);
        r = slapy2f(g, 1.0f);
        g = d[m] - p + e[l] / (g + copysignf(r, g));
        s = 1.0f; c = 1.0f; p = 0.0f;
        {
            float carr[2], sarr[2];
            for (int i = m-1; i >= l; i--) {
                f = s * e[i]; b = c * e[i];
                slartgf(g, f, &c, &s, &r);
                if (i != m-1) e[i+1] = r;
                g = d[i+1] - p;
                r = (d[i] - g)*s + 2.0f*c*b;
                p = s * r;
                d[i+1] = g + p;
                g = c*r - b;
                carr[i-l] = c; sarr[i-l] = -s;
            }
            int nrot = m - l;
            for (int j = nrot-1; j >= 0; j--) {
                float ct = carr[j], st = sarr[j];
                for (int i = 0; i < 3; i++) {
                    float tt = z[i][l+j+1];
                    z[i][l+j+1] = ct*tt - st*z[i][l+j];
                    z[i][l+j]   = st*tt + ct*z[i][l+j];
                }
            }
        }
        d[l] = d[l] - p;
        e[l] = g;
        goto L40;
L80:
        d[l] = p;
        l++;
        if (l <= lend) goto L40;
        goto L140;
    } else {
L90:
        if (l != lend) {
            for (m = l; m >= lend+1; m--) {
                float tst = e[m-1]*e[m-1];
                if (tst <= (eps2*fabsf(d[m]))*fabsf(d[m-1]) + safmin) goto L110;
            }
        }
        m = lend;
L110:
        if (m > lend) e[m-1] = 0.0f;
        p = d[l];
        if (m == l) goto L130;
        if (m == l-1) {
            slaev2f(d[l-1], e[l-1], d[l], &rt1, &rt2, &c, &s);
            for (int i = 0; i < 3; i++) {
                float tt = z[i][l];
                z[i][l]   = c*tt - s*z[i][l-1];
                z[i][l-1] = s*tt + c*z[i][l-1];
            }
            d[l-1] = rt1; d[l] = rt2; e[l-1] = 0.0f;
            l -= 2;
            if (l >= lend) goto L90;
            goto L140;
        }
        if (jtot == nmaxit) goto L140;
        jtot++;
        g = (d[l-1] - p) / (2.0f * e[l-1]);
        r = slapy2f(g, 1.0f);
        g = d[m] - p + e[l-1] / (g + copysignf(r, g));
        s = 1.0f; c = 1.0f; p = 0.0f;
        {
            float carr[2], sarr[2];
            for (int i = m; i <= l-1; i++) {
                f = s * e[i]; b = c * e[i];
                slartgf(g, f, &c, &s, &r);
                if (i != m) e[i-1] = r;
                g = d[i] - p;
                r = (d[i+1] - g)*s + 2.0f*c*b;
                p = s * r;
                d[i] = g + p;
                g = c*r - b;
                carr[i-m] = c; sarr[i-m] = s;
            }
            int nrot = l - m;
            for (int j = 0; j <= nrot-1; j++) {
                float ct = carr[j], st = sarr[j];
                for (int i = 0; i < 3; i++) {
                    float tt = z[i][m+j+1];
                    z[i][m+j+1] = ct*tt - st*z[i][m+j];
                    z[i][m+j]   = st*tt + ct*z[i][m+j];
                }
            }
        }
        d[l] = d[l] - p;
        e[l-1] = g;
        goto L90;
L130:
        d[l] = p;
        l--;
        if (l >= lend) goto L90;
        goto L140;
    }
L140:
    if (jtot < nmaxit) goto L10;
L160:
    for (int ii = 1; ii <= n-1; ii++) {
        int i = ii - 1, k = i;
        p = d[i];
        for (int j = ii; j <= n-1; j++) {
            if (d[j] < p) { k = j; p = d[j]; }
        }
        if (k != i) {
            d[k] = d[i]; d[i] = p;
            for (int row = 0; row < 3; row++) {
                float tt = z[row][i]; z[row][i] = z[row][k]; z[row][k] = tt;
            }
        }
    }
}

__device__ void ssyevd3(float a11, float a21, float a31,
                        float a22, float a32, float a33,
                        float* d, float z[3][3]) {
    float alpha = a21;
    float xnorm = fabsf(a31);
    float beta, taui, v2;
    if (xnorm == 0.0f) { taui = 0.0f; beta = alpha; v2 = 0.0f; }
    else {
        beta = -copysignf(slapy2f(alpha, xnorm), alpha);
        taui = (beta - alpha) / beta;
        v2   = a31 / (alpha - beta);
    }
    float e[2];
    e[0] = beta;
    if (taui != 0.0f) {
        float w1 = taui * (a22*1.0f + a32*v2);
        float w2 = taui * (a32*1.0f + a33*v2);
        float al = -0.5f * taui * (w1*1.0f + w2*v2);
        w1 = w1 + al*1.0f;
        w2 = w2 + al*v2;
        a22 = a22 - (1.0f*w1 + w1*1.0f);
        a32 = a32 - (v2*w1 + w2*1.0f);
        a33 = a33 - (v2*w2 + w2*v2);
    }
    d[0] = a11; d[1] = a22; d[2] = a33;
    e[1] = a32;
    z[0][0] = 1.0f; z[0][1] = 0.0f; z[0][2] = 0.0f;
    z[1][0] = 0.0f; z[2][0] = 0.0f;
    z[1][1] = 1.0f - taui;
    z[1][2] = -taui * v2;
    z[2][1] = -taui * v2;
    z[2][2] = 1.0f - (taui * v2) * v2;
    ssteqr3(d, e, z);
}

// ---------------- stage 2: frames + tangent coords + bbox --------------------
__global__ void frames_kernel(const float* __restrict__ pts) {
    int i = blockIdx.x * blockDim.x + threadIdx.x;
    if (i >= N) return;
    const int* idx = g_idx + i*KK;
    float mx = 0.f, my = 0.f, mz = 0.f;
    for (int r = 0; r < KK; r++) {
        int j = idx[r];
        mx += pts[3*j+0]; my += pts[3*j+1]; mz += pts[3*j+2];
    }
    mx /= 50.0f; my /= 50.0f; mz /= 50.0f;
    float A00=0.f, A01=0.f, A02=0.f, A11=0.f, A12=0.f, A22=0.f;
    for (int r = 0; r < KK; r++) {
        int j = idx[r];
        float cx = pts[3*j+0]-mx, cy = pts[3*j+1]-my, cz = pts[3*j+2]-mz;
        A00 += cx*cx; A01 += cx*cy; A02 += cx*cz;
        A11 += cy*cy; A12 += cy*cz; A22 += cz*cz;
    }
    A00*=0.5f; A01*=0.5f; A02*=0.5f; A11*=0.5f; A12*=0.5f; A22*=0.5f;

    float d[3];
    float V[3][3];
    ssyevd3(A00, A01, A02, A11, A12, A22, d, V);

    float nx  = V[0][0], ny  = V[1][0], nz  = V[2][0];
    float t1x = V[0][1], t1y = V[1][1], t1z = V[2][1];
    float t2x = V[0][2], t2y = V[1][2], t2z = V[2][2];
    float det = nx*(t1y*t2z - t1z*t2y)
              - ny*(t1x*t2z - t1z*t2x)
              + nz*(t1x*t2y - t1y*t2x);
    t1x *= det; t1y *= det; t1z *= det;
    g_nrm[3*i+0]=nx;  g_nrm[3*i+1]=ny;  g_nrm[3*i+2]=nz;
    g_t1 [3*i+0]=t1x; g_t1 [3*i+1]=t1y; g_t1 [3*i+2]=t1z;
    g_t2 [3*i+0]=t2x; g_t2 [3*i+1]=t2y; g_t2 [3*i+2]=t2z;
    float px = pts[3*i+0], py = pts[3*i+1], pz = pts[3*i+2];
    float bminx = INFINITY, bminy = INFINITY, bmaxx = -INFINITY, bmaxy = -INFINITY;
    for (int r = 0; r < KK; r++) {
        int j = idx[r];
        float dx = pts[3*j+0]-px, dy = pts[3*j+1]-py, dz = pts[3*j+2]-pz;
        float a0 = (dx*t1x + dy*t1y) + dz*t1z;
        float a1 = (dx*t2x + dy*t2y) + dz*t2z;
        g_dt[(i*KK+r)*2+0] = a0;
        g_dt[(i*KK+r)*2+1] = a1;
        bminx = fminf(bminx, a0); bmaxx = fmaxf(bmaxx, a0);
        bminy = fminf(bminy, a1); bmaxy = fmaxf(bmaxy, a1);
    }
    bminx *= 1.1f; bminy *= 1.1f; bmaxx *= 1.1f; bmaxy *= 1.1f;
    float ml = fmaxf(bmaxx - bminx, bmaxy - bminy);
    g_maxlen[i] = ml;
    for (int r = 0; r < KK; r++) {
        float a0 = g_dt[(i*KK+r)*2+0];
        float a1 = g_dt[(i*KK+r)*2+1];
        g_coords[(i*KK+r)*2+0] = (a0 - bminx)/ml*2.0f - 1.0f;
        g_coords[(i*KK+r)*2+1] = (a1 - bminy)/ml*2.0f - 1.0f;
    }
}

// ---------------- stage 3: shape operator + gaussian curvature ---------------
__global__ void gauss_kernel() {
    int i = blockIdx.x * blockDim.x + threadIdx.x;
    if (i >= N) return;
    const int* idx = g_idx + i*KK;
    float n0x = g_nrm[3*i+0], n0y = g_nrm[3*i+1], n0z = g_nrm[3*i+2];
    float t1x = g_t1[3*i+0],  t1y = g_t1[3*i+1],  t1z = g_t1[3*i+2];
    float t2x = g_t2[3*i+0],  t2y = g_t2[3*i+1],  t2z = g_t2[3*i+2];
    float xx=0.f, xy=0.f, yy=0.f;
    float y00=0.f, y01=0.f, y10=0.f, y11=0.f;
    for (int r = 0; r < KK; r++) {
        int j = idx[r];
        float lnx = g_nrm[3*j+0] - n0x;
        float lny = g_nrm[3*j+1] - n0y;
        float lnz = g_nrm[3*j+2] - n0z;
        float dn0 = (lnx*t1x + lny*t1y) + lnz*t1z;
        float dn1 = (lnx*t2x + lny*t2y) + lnz*t2z;
        float dt0 = g_dt[(i*KK+r)*2+0];
        float dt1 = g_dt[(i*KK+r)*2+1];
        xx += dt0*dt0; xy += dt0*dt1; yy += dt1*dt1;
        y00 += dn0*dt0; y01 += dn0*dt1;
        y10 += dn1*dt0; y11 += dn1*dt1;
    }
    float S00 = y00 + y00, S01 = y01 + y10, S11 = y11 + y11;
    float tr = xx + yy, df = xx - yy;
    float disc = sqrtf(df*df + 4.0f*xy*xy);
    float a = 0.5f*(tr - disc), b = 0.5f*(tr + disc);
    float vx = xy, vy = b - xx;
    float nn = sqrtf(vx*vx + vy*vy);
    if (nn > 0.0f) { vx /= nn; vy /= nn; }
    else           { vx = 1.0f; vy = 0.0f; }
    float q00 = vy, q10 = -vx, q01 = vx, q11 = vy;
    float sq00 = S00*q00 + S01*q10, sq01 = S00*q01 + S01*q11;
    float sq10 = S01*q00 + S11*q10, sq11 = S01*q01 + S11*q11;
    float m00 = q00*sq00 + q10*sq10;
    float m01 = q00*sq01 + q10*sq11;
    float m10 = q01*sq00 + q11*sq10;
    float m11 = q01*sq01 + q11*sq11;
    float E00 = m00 / (2.0f*a  + 1e-8f);
    float E01 = m01 / ((a + b) + 1e-8f);
    float E10 = m10 / ((a + b) + 1e-8f);
    float E11 = m11 / (2.0f*b  + 1e-8f);
    float u00 = q00*E00 + q01*E10, u01 = q00*E01 + q01*E11;
    float u10 = q10*E00 + q11*E10, u11 = q10*E01 + q11*E11;
    float w00 = u00*q00 + u01*q01;
    float w01 = u00*q10 + u01*q11;
    float w10 = u10*q00 + u11*q01;
    float w11 = u10*q10 + u11*q11;
    g_gauss[i] = w00*w11 - w01*w10;
}

// ---------------- stage 4: Voronoi cell count (argmin == 0) ------------------
__global__ void voronoi_kernel() {
    __shared__ float sx[KK], sy[KK];
    __shared__ int   part[128];
    int i = blockIdx.x;
    int t = threadIdx.x;
    if (t < KK) {
        sx[t] = g_coords[(i*KK+t)*2+0];
        sy[t] = g_coords[(i*KK+t)*2+1];
    }
    __syncthreads();
    const float step = 2.0f / 63.0f;
    int cnt = 0;
    float s0x = sx[0], s0y = sy[0];
    for (int c = t; c < NG; c += 128) {
        int a = c >> 6, b = c & 63;
        float gx = -1.0f + (float)a * step;
        float gy = -1.0f + (float)b * step;
        float dx = gx - s0x, dy = gy - s0y;
        float d0 = dx*dx + dy*dy;
        bool win = true;
        for (int j = 1; j < KK; j++) {
            float ex = gx - sx[j], ey = gy - sy[j];
            float dj = ex*ex + ey*ey;
            if (dj < d0) { win = false; break; }
        }
        cnt += win ? 1 : 0;
    }
    part[t] = cnt;
    __syncthreads();
    for (int s = 64; s > 0; s >>= 1) {
        if (t < s) part[t] += part[t+s];
        __syncthreads();
    }
    if (t == 0) g_counts[i] = part[0];
}

// ---------------- stage 5: final reduction -----------------------------------
__global__ void final_kernel(float* __restrict__ out) {
    __shared__ double sh[256];
    int t = threadIdx.x;
    double acc = 0.0;
    for (int i = t; i < N; i += 256) {
        float ml = g_maxlen[i];
        float area = (float)g_counts[i] * (ml*ml) / 3969.0f;
        acc += (double)(g_gauss[i] * area);
    }
    sh[t] = acc;
    __syncthreads();
    for (int s = 128; s > 0; s >>= 1) {
        if (t < s) sh[t] += sh[t+s];
        __syncthreads();
    }
    if (t == 0) {
        float v = (float)sh[0];
        v = v / 2.0f;
        v = v / 3.14159274101257324f;
        out[0] = v;
    }
}

// ---------------- launch ------------------------------------------------------
extern "C" void kernel_launch(void* const* d_in, const int* in_sizes, int n_in,
                              void* d_out, int out_size) {
    const float* pts = (const float*)d_in[0];
    float* out = (float*)d_out;
    zero_kernel    <<<(NC+255)/256, 256>>>();
    assign_kernel  <<<(N+255)/256, 256>>>(pts);
    prefix_kernel  <<<1, 1024>>>();
    scatter_kernel <<<(N+255)/256, 256>>>(pts);
    knn_grid_kernel<<<N/4, 128>>>(pts);
    frames_kernel  <<<N/32, 32>>>(pts);
    gauss_kernel   <<<N/32, 32>>>();
    voronoi_kernel <<<N, 128>>>();
    final_kernel   <<<1, 256>>>(out);
}

// round 5
// speedup vs baseline: 3.0759x; 3.0759x over previous
#include <cuda_runtime.h>
#include <math.h>

#define N    4096
#define KK   50
#define LW   64
#define NG   (LW*LW)
#define CAP  2048          // candidate list capacity (superset of top-50)
#define TS   256           // knn block threads

// ---------------- scratch (device globals; no allocation allowed) -------------
__device__ int    g_idx[N*KK];
__device__ float  g_nrm[N*3];
__device__ float  g_t1[N*3];
__device__ float  g_t2[N*3];
__device__ float  g_dt[N*KK*2];
__device__ float  g_coords[N*KK*2];
__device__ float  g_maxlen[N];
__device__ int    g_counts[N];
__device__ float  g_gauss[N];

// order-preserving float->uint map (ascending)
__device__ __forceinline__ unsigned fmap(float f) {
    unsigned u = __float_as_uint(f);
    return (u & 0x80000000u) ? ~u : (u | 0x80000000u);
}

// ---------------- stage 1: brute-force KNN + radix select --------------------
// One block per query. Distances use the bit-identical formula of the passing
// kernel; selection = 1024-bin histogram on the key's top 10 bits -> rank-50
// bin -> compact candidates -> exact 50-round (key,idx) min-extraction by one
// warp. g_idx is bit-identical to the tree-extraction version.
__global__ __launch_bounds__(TS) void knn_select_kernel(const float* __restrict__ pts) {
    __shared__ unsigned skey[N];                 // 16 KB
    __shared__ int      shist[1024];             // 4 KB
    __shared__ unsigned long long slist[CAP];    // 16 KB
    __shared__ int      pa[TS], pb[TS];          // 2 KB
    __shared__ int      scount;
    __shared__ int      sbstar;

    int i = blockIdx.x;
    int t = threadIdx.x;
    float xi = pts[3*i+0], yi = pts[3*i+1], zi = pts[3*i+2];
    float d2i = (xi*xi + yi*yi) + zi*zi;          // EXACT same expression

    for (int b = t; b < 1024; b += TS) shist[b] = 0;
    if (t == 0) { scount = 0; sbstar = 1023; }
    __syncthreads();

    // distances + keys + histogram
    #pragma unroll 4
    for (int j = t; j < N; j += TS) {
        float x = pts[3*j+0], y = pts[3*j+1], z = pts[3*j+2];
        float dot = (xi*x + yi*y) + zi*z;
        float d2j = (x*x + y*y) + z*z;            // EXACT same expression
        float sd  = (d2i - 2.0f*dot) + d2j;       // EXACT same expression
        unsigned key = fmap(sd);
        skey[j] = key;
        atomicAdd(&shist[key >> 22], 1);
    }
    __syncthreads();

    // block scan over 1024 bins (4 bins/thread) to locate rank-50 bin
    int b0 = t * 4;
    int sum4 = shist[b0] + shist[b0+1] + shist[b0+2] + shist[b0+3];
    pa[t] = sum4;
    __syncthreads();
    int* src = pa; int* dst = pb;
    #pragma unroll
    for (int off = 1; off < TS; off <<= 1) {
        int v = src[t];
        if (t >= off) v += src[t - off];
        dst[t] = v;
        __syncthreads();
        int* tmp = src; src = dst; dst = tmp;
    }
    int ex = src[t] - sum4;                       // exclusive prefix of 4-bin groups
    int run = ex;
    #pragma unroll
    for (int u = 0; u < 4; u++) {
        int after = run + shist[b0 + u];
        if (run < KK && after >= KK) sbstar = b0 + u;   // unique crossing thread
        run = after;
    }
    __syncthreads();
    unsigned bstar = (unsigned)sbstar;

    // compact candidates (bin <= bstar): guaranteed superset of exact top-50
    for (int j = t; j < N; j += TS) {
        unsigned key = skey[j];
        if ((key >> 22) <= bstar) {
            int pos = atomicAdd(&scount, 1);
            if (pos < CAP)
                slist[pos] = ((unsigned long long)key << 32) | (unsigned)j;
        }
    }
    __syncthreads();

    // warp 0: exact 50-round (key,idx) min-extraction
    if (t < 32) {
        int lane = t;
        int M = scount < CAP ? scount : CAP;
        for (int r = 0; r < KK; r++) {
            unsigned long long best = 0xFFFFFFFFFFFFFFFFull; int bslot = 0;
            for (int s = lane; s < M; s += 32) {
                unsigned long long v = slist[s];
                if (v < best) { best = v; bslot = s; }
            }
            #pragma unroll
            for (int o = 16; o; o >>= 1) {
                unsigned long long ov = __shfl_down_sync(0xffffffffu, best, o);
                int os = __shfl_down_sync(0xffffffffu, bslot, o);
                if (ov < best) { best = ov; bslot = os; }
            }
            best  = __shfl_sync(0xffffffffu, best, 0);
            bslot = __shfl_sync(0xffffffffu, bslot, 0);
            if (lane == 0) {
                slist[bslot] = 0xFFFFFFFFFFFFFFFFull;
                g_idx[i*KK + r] = (int)(unsigned)(best & 0xFFFFFFFFu);
            }
            __syncwarp();
        }
    }
}

// =============== faithful fp32 LAPACK ports (ssyevd path for n=3) =============
__device__ __forceinline__ float slapy2f(float x, float y) {
    float xa = fabsf(x), ya = fabsf(y);
    float w = fmaxf(xa, ya), zz = fminf(xa, ya);
    if (zz == 0.0f) return w;
    float q = zz / w;
    return w * sqrtf(1.0f + q*q);
}

__device__ __forceinline__ void slartgf(float f, float g, float* c, float* s, float* r) {
    if (g == 0.0f)      { *c = 1.0f; *s = 0.0f; *r = f; }
    else if (f == 0.0f) { *c = 0.0f; *s = copysignf(1.0f, g); *r = fabsf(g); }
    else {
        float d = sqrtf(f*f + g*g);
        *c = fabsf(f) / d;
        *r = copysignf(d, f);
        *s = g / (*r);
    }
}

__device__ void slaev2f(float a, float b, float c,
                        float* rt1, float* rt2, float* cs1, float* sn1) {
    float sm  = a + c;
    float df  = a - c;
    float adf = fabsf(df);
    float tb  = b + b;
    float ab  = fabsf(tb);
    float acmx, acmn;
    if (fabsf(a) > fabsf(c)) { acmx = a; acmn = c; }
    else                     { acmx = c; acmn = a; }
    float rt;
    if (adf > ab)      rt = adf * sqrtf(1.0f + (ab/adf)*(ab/adf));
    else if (adf < ab) rt = ab  * sqrtf(1.0f + (adf/ab)*(adf/ab));
    else               rt = ab  * sqrtf(2.0f);
    int sgn1;
    if (sm < 0.0f) {
        *rt1 = 0.5f*(sm - rt); sgn1 = -1;
        *rt2 = (acmx / *rt1)*acmn - (b / *rt1)*b;
    } else if (sm > 0.0f) {
        *rt1 = 0.5f*(sm + rt); sgn1 = 1;
        *rt2 = (acmx / *rt1)*acmn - (b / *rt1)*b;
    } else {
        *rt1 = 0.5f*rt; *rt2 = -0.5f*rt; sgn1 = 1;
    }
    int sgn2;
    float cs;
    if (df >= 0.0f) { cs = df + rt; sgn2 = 1; }
    else            { cs = df - rt; sgn2 = -1; }
    float acs = fabsf(cs);
    if (acs > ab) {
        float ct = -tb / cs;
        *sn1 = 1.0f / sqrtf(1.0f + ct*ct);
        *cs1 = ct * (*sn1);
    } else {
        if (ab == 0.0f) { *cs1 = 1.0f; *sn1 = 0.0f; }
        else {
            float tn = -cs / tb;
            *cs1 = 1.0f / sqrtf(1.0f + tn*tn);
            *sn1 = tn * (*cs1);
        }
    }
    if (sgn1 == sgn2) { float tn = *cs1; *cs1 = -(*sn1); *sn1 = tn; }
}

__device__ void ssteqr3(float* d, float* e, float z[3][3]) {
    const float eps    = 5.9604645e-08f;
    const float eps2   = eps * eps;
    const float safmin = 1.1754944e-38f;
    const int   n = 3;
    const int   nmaxit = n * 30;
    int jtot = 0;
    int l1 = 0, l, m, lsv, lend, lendsv;
    float p, g, r, c, s, f, b, rt1, rt2;

L10:
    if (l1 > n-1) goto L160;
    if (l1 > 0) e[l1-1] = 0.0f;
    for (m = l1; m <= n-2; m++) {
        float tst = fabsf(e[m]);
        if (tst == 0.0f) goto L30;
        if (tst <= (sqrtf(fabsf(d[m])) * sqrtf(fabsf(d[m+1]))) * eps) {
            e[m] = 0.0f; goto L30;
        }
    }
    m = n-1;
L30:
    l = l1; lsv = l; lend = m; lendsv = lend; l1 = m + 1;
    if (lend == l) goto L10;
    {
        float anorm = 0.0f;
        for (int i = l; i <= lend; i++)   anorm = fmaxf(anorm, fabsf(d[i]));
        for (int i = l; i <= lend-1; i++) anorm = fmaxf(anorm, fabsf(e[i]));
        if (anorm == 0.0f) goto L10;
    }
    if (fabsf(d[lend]) < fabsf(d[l])) { lend = lsv; l = lendsv; }
    if (lend > l) {
L40:
        if (l != lend) {
            for (m = l; m <= lend-1; m++) {
                float tst = e[m]*e[m];
                if (tst <= (eps2*fabsf(d[m]))*fabsf(d[m+1]) + safmin) goto L60;
            }
        }
        m = lend;
L60:
        if (m < lend) e[m] = 0.0f;
        p = d[l];
        if (m == l) goto L80;
        if (m == l+1) {
            slaev2f(d[l], e[l], d[l+1], &rt1, &rt2, &c, &s);
            for (int i = 0; i < 3; i++) {
                float tt = z[i][l+1];
                z[i][l+1] = c*tt - s*z[i][l];
                z[i][l]   = s*tt + c*z[i][l];
            }
            d[l] = rt1; d[l+1] = rt2; e[l] = 0.0f;
            l += 2;
            if (l <= lend) goto L40;
            goto L140;
        }
        if (jtot == nmaxit) goto L140;
        jtot++;
        g = (d[l+1] - p) / (2.0f * e[l]);
        r = slapy2f(g, 1.0f);
        g = d[m] - p + e[l] / (g + copysignf(r, g));
        s = 1.0f; c = 1.0f; p = 0.0f;
        {
            float carr[2], sarr[2];
            for (int i = m-1; i >= l; i--) {
                f = s * e[i]; b = c * e[i];
                slartgf(g, f, &c, &s, &r);
                if (i != m-1) e[i+1] = r;
                g = d[i+1] - p;
                r = (d[i] - g)*s + 2.0f*c*b;
                p = s * r;
                d[i+1] = g + p;
                g = c*r - b;
                carr[i-l] = c; sarr[i-l] = -s;
            }
            int nrot = m - l;
            for (int j = nrot-1; j >= 0; j--) {
                float ct = carr[j], st = sarr[j];
                for (int i = 0; i < 3; i++) {
                    float tt = z[i][l+j+1];
                    z[i][l+j+1] = ct*tt - st*z[i][l+j];
                    z[i][l+j]   = st*tt + ct*z[i][l+j];
                }
            }
        }
        d[l] = d[l] - p;
        e[l] = g;
        goto L40;
L80:
        d[l] = p;
        l++;
        if (l <= lend) goto L40;
        goto L140;
    } else {
L90:
        if (l != lend) {
            for (m = l; m >= lend+1; m--) {
                float tst = e[m-1]*e[m-1];
                if (tst <= (eps2*fabsf(d[m]))*fabsf(d[m-1]) + safmin) goto L110;
            }
        }
        m = lend;
L110:
        if (m > lend) e[m-1] = 0.0f;
        p = d[l];
        if (m == l) goto L130;
        if (m == l-1) {
            slaev2f(d[l-1], e[l-1], d[l], &rt1, &rt2, &c, &s);
            for (int i = 0; i < 3; i++) {
                float tt = z[i][l];
                z[i][l]   = c*tt - s*z[i][l-1];
                z[i][l-1] = s*tt + c*z[i][l-1];
            }
            d[l-1] = rt1; d[l] = rt2; e[l-1] = 0.0f;
            l -= 2;
            if (l >= lend) goto L90;
            goto L140;
        }
        if (jtot == nmaxit) goto L140;
        jtot++;
        g = (d[l-1] - p) / (2.0f * e[l-1]);
        r = slapy2f(g, 1.0f);
        g = d[m] - p + e[l-1] / (g + copysignf(r, g));
        s = 1.0f; c = 1.0f; p = 0.0f;
        {
            float carr[2], sarr[2];
            for (int i = m; i <= l-1; i++) {
                f = s * e[i]; b = c * e[i];
                slartgf(g, f, &c, &s, &r);
                if (i != m) e[i-1] = r;
                g = d[i] - p;
                r = (d[i+1] - g)*s + 2.0f*c*b;
                p = s * r;
                d[i] = g + p;
                g = c*r - b;
                carr[i-m] = c; sarr[i-m] = s;
            }
            int nrot = l - m;
            for (int j = 0; j <= nrot-1; j++) {
                float ct = carr[j], st = sarr[j];
                for (int i = 0; i < 3; i++) {
                    float tt = z[i][m+j+1];
                    z[i][m+j+1] = ct*tt - st*z[i][m+j];
                    z[i][m+j]   = st*tt + ct*z[i][m+j];
                }
            }
        }
        d[l] = d[l] - p;
        e[l-1] = g;
        goto L90;
L130:
        d[l] = p;
        l--;
        if (l >= lend) goto L90;
        goto L140;
    }
L140:
    if (jtot < nmaxit) goto L10;
L160:
    for (int ii = 1; ii <= n-1; ii++) {
        int i = ii - 1, k = i;
        p = d[i];
        for (int j = ii; j <= n-1; j++) {
            if (d[j] < p) { k = j; p = d[j]; }
        }
        if (k != i) {
            d[k] = d[i]; d[i] = p;
            for (int row = 0; row < 3; row++) {
                float tt = z[row][i]; z[row][i] = z[row][k]; z[row][k] = tt;
            }
        }
    }
}

__device__ void ssyevd3(float a11, float a21, float a31,
                        float a22, float a32, float a33,
                        float* d, float z[3][3]) {
    float alpha = a21;
    float xnorm = fabsf(a31);
    float beta, taui, v2;
    if (xnorm == 0.0f) { taui = 0.0f; beta = alpha; v2 = 0.0f; }
    else {
        beta = -copysignf(slapy2f(alpha, xnorm), alpha);
        taui = (beta - alpha) / beta;
        v2   = a31 / (alpha - beta);
    }
    float e[2];
    e[0] = beta;
    if (taui != 0.0f) {
        float w1 = taui * (a22*1.0f + a32*v2);
        float w2 = taui * (a32*1.0f + a33*v2);
        float al = -0.5f * taui * (w1*1.0f + w2*v2);
        w1 = w1 + al*1.0f;
        w2 = w2 + al*v2;
        a22 = a22 - (1.0f*w1 + w1*1.0f);
        a32 = a32 - (v2*w1 + w2*1.0f);
        a33 = a33 - (v2*w2 + w2*v2);
    }
    d[0] = a11; d[1] = a22; d[2] = a33;
    e[1] = a32;
    z[0][0] = 1.0f; z[0][1] = 0.0f; z[0][2] = 0.0f;
    z[1][0] = 0.0f; z[2][0] = 0.0f;
    z[1][1] = 1.0f - taui;
    z[1][2] = -taui * v2;
    z[2][1] = -taui * v2;
    z[2][2] = 1.0f - (taui * v2) * v2;
    ssteqr3(d, e, z);
}

// ---------------- stage 2: frames + tangent coords + bbox --------------------
// pts staged in smem (48KB) so the 3 gather loops hit smem (29cyc) not L2.
// Arithmetic order identical to the passing kernel.
__global__ __launch_bounds__(64) void frames_kernel(const float* __restrict__ pts) {
    __shared__ float sp[3*N];                    // 48 KB
    int t = threadIdx.x;
    for (int u = t; u < 3*N; u += 64) sp[u] = pts[u];
    __syncthreads();

    int i = blockIdx.x * 64 + t;
    const int* idx = g_idx + i*KK;
    float mx = 0.f, my = 0.f, mz = 0.f;
    for (int r = 0; r < KK; r++) {
        int j = idx[r];
        mx += sp[3*j+0]; my += sp[3*j+1]; mz += sp[3*j+2];
    }
    mx /= 50.0f; my /= 50.0f; mz /= 50.0f;
    float A00=0.f, A01=0.f, A02=0.f, A11=0.f, A12=0.f, A22=0.f;
    for (int r = 0; r < KK; r++) {
        int j = idx[r];
        float cx = sp[3*j+0]-mx, cy = sp[3*j+1]-my, cz = sp[3*j+2]-mz;
        A00 += cx*cx; A01 += cx*cy; A02 += cx*cz;
        A11 += cy*cy; A12 += cy*cz; A22 += cz*cz;
    }
    A00*=0.5f; A01*=0.5f; A02*=0.5f; A11*=0.5f; A12*=0.5f; A22*=0.5f;

    float d[3];
    float V[3][3];
    ssyevd3(A00, A01, A02, A11, A12, A22, d, V);

    float nx  = V[0][0], ny  = V[1][0], nz  = V[2][0];
    float t1x = V[0][1], t1y = V[1][1], t1z = V[2][1];
    float t2x = V[0][2], t2y = V[1][2], t2z = V[2][2];
    float det = nx*(t1y*t2z - t1z*t2y)
              - ny*(t1x*t2z - t1z*t2x)
              + nz*(t1x*t2y - t1y*t2x);
    t1x *= det; t1y *= det; t1z *= det;
    g_nrm[3*i+0]=nx;  g_nrm[3*i+1]=ny;  g_nrm[3*i+2]=nz;
    g_t1 [3*i+0]=t1x; g_t1 [3*i+1]=t1y; g_t1 [3*i+2]=t1z;
    g_t2 [3*i+0]=t2x; g_t2 [3*i+1]=t2y; g_t2 [3*i+2]=t2z;
    float px = sp[3*i+0], py = sp[3*i+1], pz = sp[3*i+2];
    float bminx = INFINITY, bminy = INFINITY, bmaxx = -INFINITY, bmaxy = -INFINITY;
    for (int r = 0; r < KK; r++) {
        int j = idx[r];
        float dx = sp[3*j+0]-px, dy = sp[3*j+1]-py, dz = sp[3*j+2]-pz;
        float a0 = (dx*t1x + dy*t1y) + dz*t1z;
        float a1 = (dx*t2x + dy*t2y) + dz*t2z;
        g_dt[(i*KK+r)*2+0] = a0;
        g_dt[(i*KK+r)*2+1] = a1;
        bminx = fminf(bminx, a0); bmaxx = fmaxf(bmaxx, a0);
        bminy = fminf(bminy, a1); bmaxy = fmaxf(bmaxy, a1);
    }
    bminx *= 1.1f; bminy *= 1.1f; bmaxx *= 1.1f; bmaxy *= 1.1f;
    float ml = fmaxf(bmaxx - bminx, bmaxy - bminy);
    g_maxlen[i] = ml;
    for (int r = 0; r < KK; r++) {
        float a0 = g_dt[(i*KK+r)*2+0];
        float a1 = g_dt[(i*KK+r)*2+1];
        g_coords[(i*KK+r)*2+0] = (a0 - bminx)/ml*2.0f - 1.0f;
        g_coords[(i*KK+r)*2+1] = (a1 - bminy)/ml*2.0f - 1.0f;
    }
}

// ---------------- stage 3: shape operator + gaussian curvature ---------------
// g_nrm staged in smem for the neighbor-normal gathers.
__global__ __launch_bounds__(64) void gauss_kernel() {
    __shared__ float sn[3*N];                    // 48 KB
    int t = threadIdx.x;
    for (int u = t; u < 3*N; u += 64) sn[u] = g_nrm[u];
    __syncthreads();

    int i = blockIdx.x * 64 + t;
    const int* idx = g_idx + i*KK;
    float n0x = sn[3*i+0], n0y = sn[3*i+1], n0z = sn[3*i+2];
    float t1x = g_t1[3*i+0],  t1y = g_t1[3*i+1],  t1z = g_t1[3*i+2];
    float t2x = g_t2[3*i+0],  t2y = g_t2[3*i+1],  t2z = g_t2[3*i+2];
    float xx=0.f, xy=0.f, yy=0.f;
    float y00=0.f, y01=0.f, y10=0.f, y11=0.f;
    for (int r = 0; r < KK; r++) {
        int j = idx[r];
        float lnx = sn[3*j+0] - n0x;
        float lny = sn[3*j+1] - n0y;
        float lnz = sn[3*j+2] - n0z;
        float dn0 = (lnx*t1x + lny*t1y) + lnz*t1z;
        float dn1 = (lnx*t2x + lny*t2y) + lnz*t2z;
        float dt0 = g_dt[(i*KK+r)*2+0];
        float dt1 = g_dt[(i*KK+r)*2+1];
        xx += dt0*dt0; xy += dt0*dt1; yy += dt1*dt1;
        y00 += dn0*dt0; y01 += dn0*dt1;
        y10 += dn1*dt0; y11 += dn1*dt1;
    }
    float S00 = y00 + y00, S01 = y01 + y10, S11 = y11 + y11;
    float tr = xx + yy, df = xx - yy;
    float disc = sqrtf(df*df + 4.0f*xy*xy);
    float a = 0.5f*(tr - disc), b = 0.5f*(tr + disc);
    float vx = xy, vy = b - xx;
    float nn = sqrtf(vx*vx + vy*vy);
    if (nn > 0.0f) { vx /= nn; vy /= nn; }
    else           { vx = 1.0f; vy = 0.0f; }
    float q00 = vy, q10 = -vx, q01 = vx, q11 = vy;
    float sq00 = S00*q00 + S01*q10, sq01 = S00*q01 + S01*q11;
    float sq10 = S01*q00 + S11*q10, sq11 = S01*q01 + S11*q11;
    float m00 = q00*sq00 + q10*sq10;
    float m01 = q00*sq01 + q10*sq11;
    float m10 = q01*sq00 + q11*sq10;
    float m11 = q01*sq01 + q11*sq11;
    float E00 = m00 / (2.0f*a  + 1e-8f);
    float E01 = m01 / ((a + b) + 1e-8f);
    float E10 = m10 / ((a + b) + 1e-8f);
    float E11 = m11 / (2.0f*b  + 1e-8f);
    float u00 = q00*E00 + q01*E10, u01 = q00*E01 + q01*E11;
    float u10 = q10*E00 + q11*E10, u11 = q10*E01 + q11*E11;
    float w00 = u00*q00 + u01*q01;
    float w01 = u00*q10 + u01*q11;
    float w10 = u10*q00 + u11*q01;
    float w11 = u10*q10 + u11*q11;
    g_gauss[i] = w00*w11 - w01*w10;
}

// ---------------- stage 4: Voronoi cell count (argmin == 0) ------------------
__global__ void voronoi_kernel() {
    __shared__ float sx[KK], sy[KK];
    __shared__ int   part[128];
    int i = blockIdx.x;
    int t = threadIdx.x;
    if (t < KK) {
        sx[t] = g_coords[(i*KK+t)*2+0];
        sy[t] = g_coords[(i*KK+t)*2+1];
    }
    __syncthreads();
    const float step = 2.0f / 63.0f;
    int cnt = 0;
    float s0x = sx[0], s0y = sy[0];
    for (int c = t; c < NG; c += 128) {
        int a = c >> 6, b = c & 63;
        float gx = -1.0f + (float)a * step;
        float gy = -1.0f + (float)b * step;
        float dx = gx - s0x, dy = gy - s0y;
        float d0 = dx*dx + dy*dy;
        bool win = true;
        for (int j = 1; j < KK; j++) {
            float ex = gx - sx[j], ey = gy - sy[j];
            float dj = ex*ex + ey*ey;
            if (dj < d0) { win = false; break; }
        }
        cnt += win ? 1 : 0;
    }
    part[t] = cnt;
    __syncthreads();
    for (int s = 64; s > 0; s >>= 1) {
        if (t < s) part[t] += part[t+s];
        __syncthreads();
    }
    if (t == 0) g_counts[i] = part[0];
}

// ---------------- stage 5: final reduction -----------------------------------
__global__ void final_kernel(float* __restrict__ out) {
    __shared__ double sh[256];
    int t = threadIdx.x;
    double acc = 0.0;
    for (int i = t; i < N; i += 256) {
        float ml = g_maxlen[i];
        float area = (float)g_counts[i] * (ml*ml) / 3969.0f;
        acc += (double)(g_gauss[i] * area);
    }
    sh[t] = acc;
    __syncthreads();
    for (int s = 128; s > 0; s >>= 1) {
        if (t < s) sh[t] += sh[t+s];
        __syncthreads();
    }
    if (t == 0) {
        float v = (float)sh[0];
        v = v / 2.0f;
        v = v / 3.14159274101257324f;
        out[0] = v;
    }
}

// ---------------- launch ------------------------------------------------------
extern "C" void kernel_launch(void* const* d_in, const int* in_sizes, int n_in,
                              void* d_out, int out_size) {
    const float* pts = (const float*)d_in[0];
    float* out = (float*)d_out;
    knn_select_kernel<<<N, TS>>>(pts);
    frames_kernel    <<<N/64, 64>>>(pts);
    gauss_kernel     <<<N/64, 64>>>();
    voronoi_kernel   <<<N, 128>>>();
    final_kernel     <<<1, 256>>>(out);
}

// round 6
// speedup vs baseline: 4.5012x; 1.4634x over previous
#include <cuda_runtime.h>
#include <math.h>

#define N    4096
#define KK   50
#define LW   64
#define NG   (LW*LW)
#define TS   256           // knn block threads
#define QB   4             // queries per knn block
#define CAP  1024          // per-query candidate capacity

// ---------------- scratch (device globals; no allocation allowed) -------------
__device__ int    g_idx[N*KK];
__device__ float  g_nrm[N*3];
__device__ float  g_t1[N*3];
__device__ float  g_t2[N*3];
__device__ float  g_dt[N*KK*2];
__device__ float2 g_coords2[N*KK];
__device__ float  g_maxlen[N];
__device__ int    g_counts[N];
__device__ float  g_gauss[N];

// order-preserving float->uint map (ascending)
__device__ __forceinline__ unsigned fmap(float f) {
    unsigned u = __float_as_uint(f);
    return (u & 0x80000000u) ? ~u : (u | 0x80000000u);
}

// ---------------- stage 1: brute-force KNN, 4 queries per block ---------------
// Pass 1: stream all points once, histogram key>>22 per query (keys not stored).
// Pass 2: recompute keys, compact candidates with bin <= bstar (superset of
// exact top-50). Extraction: rank-by-counting over unique (key,idx) u64 keys —
// bit-identical g_idx vs the serial min-extraction.
__global__ __launch_bounds__(TS) void knn_q4_kernel(const float* __restrict__ pts) {
    __shared__ int                shist[QB][1024];   // 16 KB
    __shared__ unsigned long long slist[QB][CAP];    // 32 KB
    __shared__ int   pa[TS], pb[TS];
    __shared__ int   scnt[QB];
    __shared__ int   sbstar[QB];

    int t = threadIdx.x;
    int i0 = blockIdx.x * QB;

    float qx[QB], qy[QB], qz[QB], qd2[QB];
    #pragma unroll
    for (int q = 0; q < QB; q++) {
        float x = pts[3*(i0+q)+0], y = pts[3*(i0+q)+1], z = pts[3*(i0+q)+2];
        qx[q] = x; qy[q] = y; qz[q] = z;
        qd2[q] = (x*x + y*y) + z*z;                 // EXACT expression
    }

    for (int b = t; b < QB*1024; b += TS) ((int*)shist)[b] = 0;
    if (t < QB) { scnt[t] = 0; sbstar[t] = 1023; }
    __syncthreads();

    // pass 1: histogram
    for (int j = t; j < N; j += TS) {
        float x = pts[3*j+0], y = pts[3*j+1], z = pts[3*j+2];
        float d2j = (x*x + y*y) + z*z;              // EXACT expression
        #pragma unroll
        for (int q = 0; q < QB; q++) {
            float dot = (qx[q]*x + qy[q]*y) + qz[q]*z;
            float sd  = (qd2[q] - 2.0f*dot) + d2j;  // EXACT expression
            atomicAdd(&shist[q][fmap(sd) >> 22], 1);
        }
    }
    __syncthreads();

    // per-query: scan 1024 bins, find rank-50 bin
    for (int q = 0; q < QB; q++) {
        int b0 = t * 4;
        int h0 = shist[q][b0], h1 = shist[q][b0+1], h2 = shist[q][b0+2], h3 = shist[q][b0+3];
        int sum4 = h0 + h1 + h2 + h3;
        pa[t] = sum4;
        __syncthreads();
        int* src = pa; int* dst = pb;
        #pragma unroll
        for (int off = 1; off < TS; off <<= 1) {
            int v = src[t];
            if (t >= off) v += src[t - off];
            dst[t] = v;
            __syncthreads();
            int* tmp = src; src = dst; dst = tmp;
        }
        int run = src[t] - sum4;
        int hh[4] = {h0, h1, h2, h3};
        #pragma unroll
        for (int u = 0; u < 4; u++) {
            int after = run + hh[u];
            if (run < KK && after >= KK) sbstar[q] = b0 + u;
            run = after;
        }
        __syncthreads();
    }
    unsigned bs0 = (unsigned)sbstar[0], bs1 = (unsigned)sbstar[1];
    unsigned bs2 = (unsigned)sbstar[2], bs3 = (unsigned)sbstar[3];

    // pass 2: recompute + compact candidates
    for (int j = t; j < N; j += TS) {
        float x = pts[3*j+0], y = pts[3*j+1], z = pts[3*j+2];
        float d2j = (x*x + y*y) + z*z;
        unsigned bb[QB] = {bs0, bs1, bs2, bs3};
        #pragma unroll
        for (int q = 0; q < QB; q++) {
            float dot = (qx[q]*x + qy[q]*y) + qz[q]*z;
            float sd  = (qd2[q] - 2.0f*dot) + d2j;
            unsigned key = fmap(sd);
            if ((key >> 22) <= bb[q]) {
                int pos = atomicAdd(&scnt[q], 1);
                if (pos < CAP)
                    slist[q][pos] = ((unsigned long long)key << 32) | (unsigned)j;
            }
        }
    }
    __syncthreads();

    // extraction: 64 threads per query, rank = #{smaller candidates}
    {
        int q  = t >> 6;          // 0..3
        int s  = t & 63;
        int M  = scnt[q] < CAP ? scnt[q] : CAP;
        const unsigned long long* lst = slist[q];
        for (int s0 = s; s0 < M; s0 += 64) {
            unsigned long long mine = lst[s0];
            int rank = 0;
            for (int u = 0; u < M; u++) rank += (lst[u] < mine) ? 1 : 0;
            if (rank < KK)
                g_idx[(i0+q)*KK + rank] = (int)(unsigned)(mine & 0xFFFFFFFFu);
        }
    }
}

// =============== faithful fp32 LAPACK ports (ssyevd path for n=3) =============
__device__ __forceinline__ float slapy2f(float x, float y) {
    float xa = fabsf(x), ya = fabsf(y);
    float w = fmaxf(xa, ya), zz = fminf(xa, ya);
    if (zz == 0.0f) return w;
    float q = zz / w;
    return w * sqrtf(1.0f + q*q);
}

__device__ __forceinline__ void slartgf(float f, float g, float* c, float* s, float* r) {
    if (g == 0.0f)      { *c = 1.0f; *s = 0.0f; *r = f; }
    else if (f == 0.0f) { *c = 0.0f; *s = copysignf(1.0f, g); *r = fabsf(g); }
    else {
        float d = sqrtf(f*f + g*g);
        *c = fabsf(f) / d;
        *r = copysignf(d, f);
        *s = g / (*r);
    }
}

__device__ void slaev2f(float a, float b, float c,
                        float* rt1, float* rt2, float* cs1, float* sn1) {
    float sm  = a + c;
    float df  = a - c;
    float adf = fabsf(df);
    float tb  = b + b;
    float ab  = fabsf(tb);
    float acmx, acmn;
    if (fabsf(a) > fabsf(c)) { acmx = a; acmn = c; }
    else                     { acmx = c; acmn = a; }
    float rt;
    if (adf > ab)      rt = adf * sqrtf(1.0f + (ab/adf)*(ab/adf));
    else if (adf < ab) rt = ab  * sqrtf(1.0f + (adf/ab)*(adf/ab));
    else               rt = ab  * sqrtf(2.0f);
    int sgn1;
    if (sm < 0.0f) {
        *rt1 = 0.5f*(sm - rt); sgn1 = -1;
        *rt2 = (acmx / *rt1)*acmn - (b / *rt1)*b;
    } else if (sm > 0.0f) {
        *rt1 = 0.5f*(sm + rt); sgn1 = 1;
        *rt2 = (acmx / *rt1)*acmn - (b / *rt1)*b;
    } else {
        *rt1 = 0.5f*rt; *rt2 = -0.5f*rt; sgn1 = 1;
    }
    int sgn2;
    float cs;
    if (df >= 0.0f) { cs = df + rt; sgn2 = 1; }
    else            { cs = df - rt; sgn2 = -1; }
    float acs = fabsf(cs);
    if (acs > ab) {
        float ct = -tb / cs;
        *sn1 = 1.0f / sqrtf(1.0f + ct*ct);
        *cs1 = ct * (*sn1);
    } else {
        if (ab == 0.0f) { *cs1 = 1.0f; *sn1 = 0.0f; }
        else {
            float tn = -cs / tb;
            *cs1 = 1.0f / sqrtf(1.0f + tn*tn);
            *sn1 = tn * (*cs1);
        }
    }
    if (sgn1 == sgn2) { float tn = *cs1; *cs1 = -(*sn1); *sn1 = tn; }
}

__device__ void ssteqr3(float* d, float* e, float z[3][3]) {
    const float eps    = 5.9604645e-08f;
    const float eps2   = eps * eps;
    const float safmin = 1.1754944e-38f;
    const int   n = 3;
    const int   nmaxit = n * 30;
    int jtot = 0;
    int l1 = 0, l, m, lsv, lend, lendsv;
    float p, g, r, c, s, f, b, rt1, rt2;

L10:
    if (l1 > n-1) goto L160;
    if (l1 > 0) e[l1-1] = 0.0f;
    for (m = l1; m <= n-2; m++) {
        float tst = fabsf(e[m]);
        if (tst == 0.0f) goto L30;
        if (tst <= (sqrtf(fabsf(d[m])) * sqrtf(fabsf(d[m+1]))) * eps) {
            e[m] = 0.0f; goto L30;
        }
    }
    m = n-1;
L30:
    l = l1; lsv = l; lend = m; lendsv = lend; l1 = m + 1;
    if (lend == l) goto L10;
    {
        float anorm = 0.0f;
        for (int i = l; i <= lend; i++)   anorm = fmaxf(anorm, fabsf(d[i]));
        for (int i = l; i <= lend-1; i++) anorm = fmaxf(anorm, fabsf(e[i]));
        if (anorm == 0.0f) goto L10;
    }
    if (fabsf(d[lend]) < fabsf(d[l])) { lend = lsv; l = lendsv; }
    if (lend > l) {
L40:
        if (l != lend) {
            for (m = l; m <= lend-1; m++) {
                float tst = e[m]*e[m];
                if (tst <= (eps2*fabsf(d[m]))*fabsf(d[m+1]) + safmin) goto L60;
            }
        }
        m = lend;
L60:
        if (m < lend) e[m] = 0.0f;
        p = d[l];
        if (m == l) goto L80;
        if (m == l+1) {
            slaev2f(d[l], e[l], d[l+1], &rt1, &rt2, &c, &s);
            for (int i = 0; i < 3; i++) {
                float tt = z[i][l+1];
                z[i][l+1] = c*tt - s*z[i][l];
                z[i][l]   = s*tt + c*z[i][l];
            }
            d[l] = rt1; d[l+1] = rt2; e[l] = 0.0f;
            l += 2;
            if (l <= lend) goto L40;
            goto L140;
        }
        if (jtot == nmaxit) goto L140;
        jtot++;
        g = (d[l+1] - p) / (2.0f * e[l]);
        r = slapy2f(g, 1.0f);
        g = d[m] - p + e[l] / (g + copysignf(r, g));
        s = 1.0f; c = 1.0f; p = 0.0f;
        {
            float carr[2], sarr[2];
            for (int i = m-1; i >= l; i--) {
                f = s * e[i]; b = c * e[i];
                slartgf(g, f, &c, &s, &r);
                if (i != m-1) e[i+1] = r;
                g = d[i+1] - p;
                r = (d[i] - g)*s + 2.0f*c*b;
                p = s * r;
                d[i+1] = g + p;
                g = c*r - b;
                carr[i-l] = c; sarr[i-l] = -s;
            }
            int nrot = m - l;
            for (int j = nrot-1; j >= 0; j--) {
                float ct = carr[j], st = sarr[j];
                for (int i = 0; i < 3; i++) {
                    float tt = z[i][l+j+1];
                    z[i][l+j+1] = ct*tt - st*z[i][l+j];
                    z[i][l+j]   = st*tt + ct*z[i][l+j];
                }
            }
        }
        d[l] = d[l] - p;
        e[l] = g;
        goto L40;
L80:
        d[l] = p;
        l++;
        if (l <= lend) goto L40;
        goto L140;
    } else {
L90:
        if (l != lend) {
            for (m = l; m >= lend+1; m--) {
                float tst = e[m-1]*e[m-1];
                if (tst <= (eps2*fabsf(d[m]))*fabsf(d[m-1]) + safmin) goto L110;
            }
        }
        m = lend;
L110:
        if (m > lend) e[m-1] = 0.0f;
        p = d[l];
        if (m == l) goto L130;
        if (m == l-1) {
            slaev2f(d[l-1], e[l-1], d[l], &rt1, &rt2, &c, &s);
            for (int i = 0; i < 3; i++) {
                float tt = z[i][l];
                z[i][l]   = c*tt - s*z[i][l-1];
                z[i][l-1] = s*tt + c*z[i][l-1];
            }
            d[l-1] = rt1; d[l] = rt2; e[l-1] = 0.0f;
            l -= 2;
            if (l >= lend) goto L90;
            goto L140;
        }
        if (jtot == nmaxit) goto L140;
        jtot++;
        g = (d[l-1] - p) / (2.0f * e[l-1]);
        r = slapy2f(g, 1.0f);
        g = d[m] - p + e[l-1] / (g + copysignf(r, g));
        s = 1.0f; c = 1.0f; p = 0.0f;
        {
            float carr[2], sarr[2];
            for (int i = m; i <= l-1; i++) {
                f = s * e[i]; b = c * e[i];
                slartgf(g, f, &c, &s, &r);
                if (i != m) e[i-1] = r;
                g = d[i] - p;
                r = (d[i+1] - g)*s + 2.0f*c*b;
                p = s * r;
                d[i] = g + p;
                g = c*r - b;
                carr[i-m] = c; sarr[i-m] = s;
            }
            int nrot = l - m;
            for (int j = 0; j <= nrot-1; j++) {
                float ct = carr[j], st = sarr[j];
                for (int i = 0; i < 3; i++) {
                    float tt = z[i][m+j+1];
                    z[i][m+j+1] = ct*tt - st*z[i][m+j];
                    z[i][m+j]   = st*tt + ct*z[i][m+j];
                }
            }
        }
        d[l] = d[l] - p;
        e[l-1] = g;
        goto L90;
L130:
        d[l] = p;
        l--;
        if (l >= lend) goto L90;
        goto L140;
    }
L140:
    if (jtot < nmaxit) goto L10;
L160:
    for (int ii = 1; ii <= n-1; ii++) {
        int i = ii - 1, k = i;
        p = d[i];
        for (int j = ii; j <= n-1; j++) {
            if (d[j] < p) { k = j; p = d[j]; }
        }
        if (k != i) {
            d[k] = d[i]; d[i] = p;
            for (int row = 0; row < 3; row++) {
                float tt = z[row][i]; z[row][i] = z[row][k]; z[row][k] = tt;
            }
        }
    }
}

__device__ void ssyevd3(float a11, float a21, float a31,
                        float a22, float a32, float a33,
                        float* d, float z[3][3]) {
    float alpha = a21;
    float xnorm = fabsf(a31);
    float beta, taui, v2;
    if (xnorm == 0.0f) { taui = 0.0f; beta = alpha; v2 = 0.0f; }
    else {
        beta = -copysignf(slapy2f(alpha, xnorm), alpha);
        taui = (beta - alpha) / beta;
        v2   = a31 / (alpha - beta);
    }
    float e[2];
    e[0] = beta;
    if (taui != 0.0f) {
        float w1 = taui * (a22*1.0f + a32*v2);
        float w2 = taui * (a32*1.0f + a33*v2);
        float al = -0.5f * taui * (w1*1.0f + w2*v2);
        w1 = w1 + al*1.0f;
        w2 = w2 + al*v2;
        a22 = a22 - (1.0f*w1 + w1*1.0f);
        a32 = a32 - (v2*w1 + w2*1.0f);
        a33 = a33 - (v2*w2 + w2*v2);
    }
    d[0] = a11; d[1] = a22; d[2] = a33;
    e[1] = a32;
    z[0][0] = 1.0f; z[0][1] = 0.0f; z[0][2] = 0.0f;
    z[1][0] = 0.0f; z[2][0] = 0.0f;
    z[1][1] = 1.0f - taui;
    z[1][2] = -taui * v2;
    z[2][1] = -taui * v2;
    z[2][2] = 1.0f - (taui * v2) * v2;
    ssteqr3(d, e, z);
}

// ---------------- stage 2: frames + tangent coords + bbox --------------------
__global__ __launch_bounds__(32) void frames_kernel(const float* __restrict__ pts) {
    int i = blockIdx.x * 32 + threadIdx.x;
    const int* idx = g_idx + i*KK;
    float mx = 0.f, my = 0.f, mz = 0.f;
    for (int r = 0; r < KK; r++) {
        int j = idx[r];
        mx += pts[3*j+0]; my += pts[3*j+1]; mz += pts[3*j+2];
    }
    mx /= 50.0f; my /= 50.0f; mz /= 50.0f;
    float A00=0.f, A01=0.f, A02=0.f, A11=0.f, A12=0.f, A22=0.f;
    for (int r = 0; r < KK; r++) {
        int j = idx[r];
        float cx = pts[3*j+0]-mx, cy = pts[3*j+1]-my, cz = pts[3*j+2]-mz;
        A00 += cx*cx; A01 += cx*cy; A02 += cx*cz;
        A11 += cy*cy; A12 += cy*cz; A22 += cz*cz;
    }
    A00*=0.5f; A01*=0.5f; A02*=0.5f; A11*=0.5f; A12*=0.5f; A22*=0.5f;

    float d[3];
    float V[3][3];
    ssyevd3(A00, A01, A02, A11, A12, A22, d, V);

    float nx  = V[0][0], ny  = V[1][0], nz  = V[2][0];
    float t1x = V[0][1], t1y = V[1][1], t1z = V[2][1];
    float t2x = V[0][2], t2y = V[1][2], t2z = V[2][2];
    float det = nx*(t1y*t2z - t1z*t2y)
              - ny*(t1x*t2z - t1z*t2x)
              + nz*(t1x*t2y - t1y*t2x);
    t1x *= det; t1y *= det; t1z *= det;
    g_nrm[3*i+0]=nx;  g_nrm[3*i+1]=ny;  g_nrm[3*i+2]=nz;
    g_t1 [3*i+0]=t1x; g_t1 [3*i+1]=t1y; g_t1 [3*i+2]=t1z;
    g_t2 [3*i+0]=t2x; g_t2 [3*i+1]=t2y; g_t2 [3*i+2]=t2z;
    float px = pts[3*i+0], py = pts[3*i+1], pz = pts[3*i+2];
    float bminx = INFINITY, bminy = INFINITY, bmaxx = -INFINITY, bmaxy = -INFINITY;
    for (int r = 0; r < KK; r++) {
        int j = idx[r];
        float dx = pts[3*j+0]-px, dy = pts[3*j+1]-py, dz = pts[3*j+2]-pz;
        float a0 = (dx*t1x + dy*t1y) + dz*t1z;
        float a1 = (dx*t2x + dy*t2y) + dz*t2z;
        g_dt[(i*KK+r)*2+0] = a0;
        g_dt[(i*KK+r)*2+1] = a1;
        bminx = fminf(bminx, a0); bmaxx = fmaxf(bmaxx, a0);
        bminy = fminf(bminy, a1); bmaxy = fmaxf(bmaxy, a1);
    }
    bminx *= 1.1f; bminy *= 1.1f; bmaxx *= 1.1f; bmaxy *= 1.1f;
    float ml = fmaxf(bmaxx - bminx, bmaxy - bminy);
    g_maxlen[i] = ml;
    for (int r = 0; r < KK; r++) {
        float a0 = g_dt[(i*KK+r)*2+0];
        float a1 = g_dt[(i*KK+r)*2+1];
        float c0 = (a0 - bminx)/ml*2.0f - 1.0f;
        float c1 = (a1 - bminy)/ml*2.0f - 1.0f;
        g_coords2[i*KK+r] = make_float2(c0, c1);
    }
}

// ---------------- stage 3: shape operator + gaussian curvature ---------------
__global__ __launch_bounds__(32) void gauss_kernel() {
    int i = blockIdx.x * 32 + threadIdx.x;
    const int* idx = g_idx + i*KK;
    float n0x = g_nrm[3*i+0], n0y = g_nrm[3*i+1], n0z = g_nrm[3*i+2];
    float t1x = g_t1[3*i+0],  t1y = g_t1[3*i+1],  t1z = g_t1[3*i+2];
    float t2x = g_t2[3*i+0],  t2y = g_t2[3*i+1],  t2z = g_t2[3*i+2];
    float xx=0.f, xy=0.f, yy=0.f;
    float y00=0.f, y01=0.f, y10=0.f, y11=0.f;
    for (int r = 0; r < KK; r++) {
        int j = idx[r];
        float lnx = g_nrm[3*j+0] - n0x;
        float lny = g_nrm[3*j+1] - n0y;
        float lnz = g_nrm[3*j+2] - n0z;
        float dn0 = (lnx*t1x + lny*t1y) + lnz*t1z;
        float dn1 = (lnx*t2x + lny*t2y) + lnz*t2z;
        float dt0 = g_dt[(i*KK+r)*2+0];
        float dt1 = g_dt[(i*KK+r)*2+1];
        xx += dt0*dt0; xy += dt0*dt1; yy += dt1*dt1;
        y00 += dn0*dt0; y01 += dn0*dt1;
        y10 += dn1*dt0; y11 += dn1*dt1;
    }
    float S00 = y00 + y00, S01 = y01 + y10, S11 = y11 + y11;
    float tr = xx + yy, df = xx - yy;
    float disc = sqrtf(df*df + 4.0f*xy*xy);
    float a = 0.5f*(tr - disc), b = 0.5f*(tr + disc);
    float vx = xy, vy = b - xx;
    float nn = sqrtf(vx*vx + vy*vy);
    if (nn > 0.0f) { vx /= nn; vy /= nn; }
    else           { vx = 1.0f; vy = 0.0f; }
    float q00 = vy, q10 = -vx, q01 = vx, q11 = vy;
    float sq00 = S00*q00 + S01*q10, sq01 = S00*q01 + S01*q11;
    float sq10 = S01*q00 + S11*q10, sq11 = S01*q01 + S11*q11;
    float m00 = q00*sq00 + q10*sq10;
    float m01 = q00*sq01 + q10*sq11;
    float m10 = q01*sq00 + q11*sq10;
    float m11 = q01*sq01 + q11*sq11;
    float E00 = m00 / (2.0f*a  + 1e-8f);
    float E01 = m01 / ((a + b) + 1e-8f);
    float E10 = m10 / ((a + b) + 1e-8f);
    float E11 = m11 / (2.0f*b  + 1e-8f);
    float u00 = q00*E00 + q01*E10, u01 = q00*E01 + q01*E11;
    float u10 = q10*E00 + q11*E10, u11 = q10*E01 + q11*E11;
    float w00 = u00*q00 + u01*q01;
    float w01 = u00*q10 + u01*q11;
    float w10 = u10*q00 + u11*q01;
    float w11 = u10*q10 + u11*q11;
    g_gauss[i] = w00*w11 - w01*w10;
}

// ---------------- stage 4: Voronoi cell count (argmin == 0) ------------------
// Chunked branchless inner loop (8 sites per chunk), warp-uniform ballot exit.
// Each dj uses the identical arithmetic of the passing kernel -> counts
// bit-identical.
__global__ __launch_bounds__(128) void voronoi_kernel() {
    __shared__ float2 ss[KK];
    __shared__ int    part[128];
    int i = blockIdx.x;
    int t = threadIdx.x;
    if (t < KK) ss[t] = g_coords2[i*KK + t];
    __syncthreads();
    const float step = 2.0f / 63.0f;
    int cnt = 0;
    float s0x = ss[0].x, s0y = ss[0].y;
    for (int c = t; c < NG; c += 128) {
        int a = c >> 6, b = c & 63;
        float gx = -1.0f + (float)a * step;
        float gy = -1.0f + (float)b * step;
        float dx = gx - s0x, dy = gy - s0y;
        float d0 = dx*dx + dy*dy;
        bool lost = false;
        for (int j0 = 1; j0 < KK; j0 += 8) {
            #pragma unroll
            for (int jj = 0; jj < 8; jj++) {
                int j = j0 + jj;
                if (j < KK) {
                    float2 s = ss[j];
                    float ex = gx - s.x, ey = gy - s.y;
                    float dj = ex*ex + ey*ey;
                    lost = lost | (dj < d0);
                }
            }
            if (__all_sync(0xffffffffu, lost)) break;
        }
        cnt += lost ? 0 : 1;
    }
    part[t] = cnt;
    __syncthreads();
    for (int s = 64; s > 0; s >>= 1) {
        if (t < s) part[t] += part[t+s];
        __syncthreads();
    }
    if (t == 0) g_counts[i] = part[0];
}

// ---------------- stage 5: final reduction -----------------------------------
__global__ void final_kernel(float* __restrict__ out) {
    __shared__ double sh[256];
    int t = threadIdx.x;
    double acc = 0.0;
    for (int i = t; i < N; i += 256) {
        float ml = g_maxlen[i];
        float area = (float)g_counts[i] * (ml*ml) / 3969.0f;
        acc += (double)(g_gauss[i] * area);
    }
    sh[t] = acc;
    __syncthreads();
    for (int s = 128; s > 0; s >>= 1) {
        if (t < s) sh[t] += sh[t+s];
        __syncthreads();
    }
    if (t == 0) {
        float v = (float)sh[0];
        v = v / 2.0f;
        v = v / 3.14159274101257324f;
        out[0] = v;
    }
}

// ---------------- launch ------------------------------------------------------
extern "C" void kernel_launch(void* const* d_in, const int* in_sizes, int n_in,
                              void* d_out, int out_size) {
    const float* pts = (const float*)d_in[0];
    float* out = (float*)d_out;
    knn_q4_kernel<<<N/QB, TS>>>(pts);
    frames_kernel<<<N/32, 32>>>(pts);
    gauss_kernel <<<N/32, 32>>>();
    voronoi_kernel<<<N, 128>>>();
    final_kernel <<<1, 256>>>(out);
}

// round 7
// speedup vs baseline: 5.7809x; 1.2843x over previous
#include <cuda_runtime.h>
#include <math.h>

#define N    4096
#define KK   50
#define LW   64
#define NG   (LW*LW)
#define TS   256           // knn block threads
#define QB   4             // queries per knn block
#define CAP  1024          // per-query candidate capacity

// ---------------- scratch (device globals; no allocation allowed) -------------
__device__ int    g_idx[N*KK];
__device__ float  g_nrm[N*3];
__device__ float  g_t1[N*3];
__device__ float  g_t2[N*3];
__device__ float  g_dt[N*KK*2];
__device__ float2 g_coords2[N*KK];
__device__ float  g_maxlen[N];
__device__ int    g_counts[N];
__device__ float  g_gauss[N];

// order-preserving float->uint map (ascending)
__device__ __forceinline__ unsigned fmap(float f) {
    unsigned u = __float_as_uint(f);
    return (u & 0x80000000u) ? ~u : (u | 0x80000000u);
}

// ---------------- stage 1: brute-force KNN, 4 queries per block ---------------
__global__ __launch_bounds__(TS) void knn_q4_kernel(const float* __restrict__ pts) {
    __shared__ int                shist[QB][1024];   // 16 KB
    __shared__ unsigned long long slist[QB][CAP];    // 32 KB
    __shared__ int   pa[TS], pb[TS];
    __shared__ int   scnt[QB];
    __shared__ int   sbstar[QB];

    int t = threadIdx.x;
    int i0 = blockIdx.x * QB;

    float qx[QB], qy[QB], qz[QB], qd2[QB];
    #pragma unroll
    for (int q = 0; q < QB; q++) {
        float x = pts[3*(i0+q)+0], y = pts[3*(i0+q)+1], z = pts[3*(i0+q)+2];
        qx[q] = x; qy[q] = y; qz[q] = z;
        qd2[q] = (x*x + y*y) + z*z;                 // EXACT expression
    }

    for (int b = t; b < QB*1024; b += TS) ((int*)shist)[b] = 0;
    if (t < QB) { scnt[t] = 0; sbstar[t] = 1023; }
    __syncthreads();

    // pass 1: histogram
    for (int j = t; j < N; j += TS) {
        float x = pts[3*j+0], y = pts[3*j+1], z = pts[3*j+2];
        float d2j = (x*x + y*y) + z*z;              // EXACT expression
        #pragma unroll
        for (int q = 0; q < QB; q++) {
            float dot = (qx[q]*x + qy[q]*y) + qz[q]*z;
            float sd  = (qd2[q] - 2.0f*dot) + d2j;  // EXACT expression
            atomicAdd(&shist[q][fmap(sd) >> 22], 1);
        }
    }
    __syncthreads();

    // per-query: scan 1024 bins, find rank-50 bin
    for (int q = 0; q < QB; q++) {
        int b0 = t * 4;
        int h0 = shist[q][b0], h1 = shist[q][b0+1], h2 = shist[q][b0+2], h3 = shist[q][b0+3];
        int sum4 = h0 + h1 + h2 + h3;
        pa[t] = sum4;
        __syncthreads();
        int* src = pa; int* dst = pb;
        #pragma unroll
        for (int off = 1; off < TS; off <<= 1) {
            int v = src[t];
            if (t >= off) v += src[t - off];
            dst[t] = v;
            __syncthreads();
            int* tmp = src; src = dst; dst = tmp;
        }
        int run = src[t] - sum4;
        int hh[4] = {h0, h1, h2, h3};
        #pragma unroll
        for (int u = 0; u < 4; u++) {
            int after = run + hh[u];
            if (run < KK && after >= KK) sbstar[q] = b0 + u;
            run = after;
        }
        __syncthreads();
    }
    unsigned bs0 = (unsigned)sbstar[0], bs1 = (unsigned)sbstar[1];
    unsigned bs2 = (unsigned)sbstar[2], bs3 = (unsigned)sbstar[3];

    // pass 2: recompute + compact candidates
    for (int j = t; j < N; j += TS) {
        float x = pts[3*j+0], y = pts[3*j+1], z = pts[3*j+2];
        float d2j = (x*x + y*y) + z*z;
        unsigned bb[QB] = {bs0, bs1, bs2, bs3};
        #pragma unroll
        for (int q = 0; q < QB; q++) {
            float dot = (qx[q]*x + qy[q]*y) + qz[q]*z;
            float sd  = (qd2[q] - 2.0f*dot) + d2j;
            unsigned key = fmap(sd);
            if ((key >> 22) <= bb[q]) {
                int pos = atomicAdd(&scnt[q], 1);
                if (pos < CAP)
                    slist[q][pos] = ((unsigned long long)key << 32) | (unsigned)j;
            }
        }
    }
    __syncthreads();

    // extraction: 64 threads per query, rank = #{smaller candidates}
    {
        int q  = t >> 6;          // 0..3
        int s  = t & 63;
        int M  = scnt[q] < CAP ? scnt[q] : CAP;
        const unsigned long long* lst = slist[q];
        for (int s0 = s; s0 < M; s0 += 64) {
            unsigned long long mine = lst[s0];
            int rank = 0;
            for (int u = 0; u < M; u++) rank += (lst[u] < mine) ? 1 : 0;
            if (rank < KK)
                g_idx[(i0+q)*KK + rank] = (int)(unsigned)(mine & 0xFFFFFFFFu);
        }
    }
}

// =============== faithful fp32 LAPACK ports (ssyevd path for n=3) =============
__device__ __forceinline__ float slapy2f(float x, float y) {
    float xa = fabsf(x), ya = fabsf(y);
    float w = fmaxf(xa, ya), zz = fminf(xa, ya);
    if (zz == 0.0f) return w;
    float q = zz / w;
    return w * sqrtf(1.0f + q*q);
}

__device__ __forceinline__ void slartgf(float f, float g, float* c, float* s, float* r) {
    if (g == 0.0f)      { *c = 1.0f; *s = 0.0f; *r = f; }
    else if (f == 0.0f) { *c = 0.0f; *s = copysignf(1.0f, g); *r = fabsf(g); }
    else {
        float d = sqrtf(f*f + g*g);
        *c = fabsf(f) / d;
        *r = copysignf(d, f);
        *s = g / (*r);
    }
}

__device__ void slaev2f(float a, float b, float c,
                        float* rt1, float* rt2, float* cs1, float* sn1) {
    float sm  = a + c;
    float df  = a - c;
    float adf = fabsf(df);
    float tb  = b + b;
    float ab  = fabsf(tb);
    float acmx, acmn;
    if (fabsf(a) > fabsf(c)) { acmx = a; acmn = c; }
    else                     { acmx = c; acmn = a; }
    float rt;
    if (adf > ab)      rt = adf * sqrtf(1.0f + (ab/adf)*(ab/adf));
    else if (adf < ab) rt = ab  * sqrtf(1.0f + (adf/ab)*(adf/ab));
    else               rt = ab  * sqrtf(2.0f);
    int sgn1;
    if (sm < 0.0f) {
        *rt1 = 0.5f*(sm - rt); sgn1 = -1;
        *rt2 = (acmx / *rt1)*acmn - (b / *rt1)*b;
    } else if (sm > 0.0f) {
        *rt1 = 0.5f*(sm + rt); sgn1 = 1;
        *rt2 = (acmx / *rt1)*acmn - (b / *rt1)*b;
    } else {
        *rt1 = 0.5f*rt; *rt2 = -0.5f*rt; sgn1 = 1;
    }
    int sgn2;
    float cs;
    if (df >= 0.0f) { cs = df + rt; sgn2 = 1; }
    else            { cs = df - rt; sgn2 = -1; }
    float acs = fabsf(cs);
    if (acs > ab) {
        float ct = -tb / cs;
        *sn1 = 1.0f / sqrtf(1.0f + ct*ct);
        *cs1 = ct * (*sn1);
    } else {
        if (ab == 0.0f) { *cs1 = 1.0f; *sn1 = 0.0f; }
        else {
            float tn = -cs / tb;
            *cs1 = 1.0f / sqrtf(1.0f + tn*tn);
            *sn1 = tn * (*cs1);
        }
    }
    if (sgn1 == sgn2) { float tn = *cs1; *cs1 = -(*sn1); *sn1 = tn; }
}

__device__ void ssteqr3(float* d, float* e, float z[3][3]) {
    const float eps    = 5.9604645e-08f;
    const float eps2   = eps * eps;
    const float safmin = 1.1754944e-38f;
    const int   n = 3;
    const int   nmaxit = n * 30;
    int jtot = 0;
    int l1 = 0, l, m, lsv, lend, lendsv;
    float p, g, r, c, s, f, b, rt1, rt2;

L10:
    if (l1 > n-1) goto L160;
    if (l1 > 0) e[l1-1] = 0.0f;
    for (m = l1; m <= n-2; m++) {
        float tst = fabsf(e[m]);
        if (tst == 0.0f) goto L30;
        if (tst <= (sqrtf(fabsf(d[m])) * sqrtf(fabsf(d[m+1]))) * eps) {
            e[m] = 0.0f; goto L30;
        }
    }
    m = n-1;
L30:
    l = l1; lsv = l; lend = m; lendsv = lend; l1 = m + 1;
    if (lend == l) goto L10;
    {
        float anorm = 0.0f;
        for (int i = l; i <= lend; i++)   anorm = fmaxf(anorm, fabsf(d[i]));
        for (int i = l; i <= lend-1; i++) anorm = fmaxf(anorm, fabsf(e[i]));
        if (anorm == 0.0f) goto L10;
    }
    if (fabsf(d[lend]) < fabsf(d[l])) { lend = lsv; l = lendsv; }
    if (lend > l) {
L40:
        if (l != lend) {
            for (m = l; m <= lend-1; m++) {
                float tst = e[m]*e[m];
                if (tst <= (eps2*fabsf(d[m]))*fabsf(d[m+1]) + safmin) goto L60;
            }
        }
        m = lend;
L60:
        if (m < lend) e[m] = 0.0f;
        p = d[l];
        if (m == l) goto L80;
        if (m == l+1) {
            slaev2f(d[l], e[l], d[l+1], &rt1, &rt2, &c, &s);
            for (int i = 0; i < 3; i++) {
                float tt = z[i][l+1];
                z[i][l+1] = c*tt - s*z[i][l];
                z[i][l]   = s*tt + c*z[i][l];
            }
            d[l] = rt1; d[l+1] = rt2; e[l] = 0.0f;
            l += 2;
            if (l <= lend) goto L40;
            goto L140;
        }
        if (jtot == nmaxit) goto L140;
        jtot++;
        g = (d[l+1] - p) / (2.0f * e[l]);
        r = slapy2f(g, 1.0f);
        g = d[m] - p + e[l] / (g + copysignf(r, g));
        s = 1.0f; c = 1.0f; p = 0.0f;
        {
            float carr[2], sarr[2];
            for (int i = m-1; i >= l; i--) {
                f = s * e[i]; b = c * e[i];
                slartgf(g, f, &c, &s, &r);
                if (i != m-1) e[i+1] = r;
                g = d[i+1] - p;
                r = (d[i] - g)*s + 2.0f*c*b;
                p = s * r;
                d[i+1] = g + p;
                g = c*r - b;
                carr[i-l] = c; sarr[i-l] = -s;
            }
            int nrot = m - l;
            for (int j = nrot-1; j >= 0; j--) {
                float ct = carr[j], st = sarr[j];
                for (int i = 0; i < 3; i++) {
                    float tt = z[i][l+j+1];
                    z[i][l+j+1] = ct*tt - st*z[i][l+j];
                    z[i][l+j]   = st*tt + ct*z[i][l+j];
                }
            }
        }
        d[l] = d[l] - p;
        e[l] = g;
        goto L40;
L80:
        d[l] = p;
        l++;
        if (l <= lend) goto L40;
        goto L140;
    } else {
L90:
        if (l != lend) {
            for (m = l; m >= lend+1; m--) {
                float tst = e[m-1]*e[m-1];
                if (tst <= (eps2*fabsf(d[m]))*fabsf(d[m-1]) + safmin) goto L110;
            }
        }
        m = lend;
L110:
        if (m > lend) e[m-1] = 0.0f;
        p = d[l];
        if (m == l) goto L130;
        if (m == l-1) {
            slaev2f(d[l-1], e[l-1], d[l], &rt1, &rt2, &c, &s);
            for (int i = 0; i < 3; i++) {
                float tt = z[i][l];
                z[i][l]   = c*tt - s*z[i][l-1];
                z[i][l-1] = s*tt + c*z[i][l-1];
            }
            d[l-1] = rt1; d[l] = rt2; e[l-1] = 0.0f;
            l -= 2;
            if (l >= lend) goto L90;
            goto L140;
        }
        if (jtot == nmaxit) goto L140;
        jtot++;
        g = (d[l-1] - p) / (2.0f * e[l-1]);
        r = slapy2f(g, 1.0f);
        g = d[m] - p + e[l-1] / (g + copysignf(r, g));
        s = 1.0f; c = 1.0f; p = 0.0f;
        {
            float carr[2], sarr[2];
            for (int i = m; i <= l-1; i++) {
                f = s * e[i]; b = c * e[i];
                slartgf(g, f, &c, &s, &r);
                if (i != m) e[i-1] = r;
                g = d[i] - p;
                r = (d[i+1] - g)*s + 2.0f*c*b;
                p = s * r;
                d[i] = g + p;
                g = c*r - b;
                carr[i-m] = c; sarr[i-m] = s;
            }
            int nrot = l - m;
            for (int j = 0; j <= nrot-1; j++) {
                float ct = carr[j], st = sarr[j];
                for (int i = 0; i < 3; i++) {
                    float tt = z[i][m+j+1];
                    z[i][m+j+1] = ct*tt - st*z[i][m+j];
                    z[i][m+j]   = st*tt + ct*z[i][m+j];
                }
            }
        }
        d[l] = d[l] - p;
        e[l-1] = g;
        goto L90;
L130:
        d[l] = p;
        l--;
        if (l >= lend) goto L90;
        goto L140;
    }
L140:
    if (jtot < nmaxit) goto L10;
L160:
    for (int ii = 1; ii <= n-1; ii++) {
        int i = ii - 1, k = i;
        p = d[i];
        for (int j = ii; j <= n-1; j++) {
            if (d[j] < p) { k = j; p = d[j]; }
        }
        if (k != i) {
            d[k] = d[i]; d[i] = p;
            for (int row = 0; row < 3; row++) {
                float tt = z[row][i]; z[row][i] = z[row][k]; z[row][k] = tt;
            }
        }
    }
}

__device__ void ssyevd3(float a11, float a21, float a31,
                        float a22, float a32, float a33,
                        float* d, float z[3][3]) {
    float alpha = a21;
    float xnorm = fabsf(a31);
    float beta, taui, v2;
    if (xnorm == 0.0f) { taui = 0.0f; beta = alpha; v2 = 0.0f; }
    else {
        beta = -copysignf(slapy2f(alpha, xnorm), alpha);
        taui = (beta - alpha) / beta;
        v2   = a31 / (alpha - beta);
    }
    float e[2];
    e[0] = beta;
    if (taui != 0.0f) {
        float w1 = taui * (a22*1.0f + a32*v2);
        float w2 = taui * (a32*1.0f + a33*v2);
        float al = -0.5f * taui * (w1*1.0f + w2*v2);
        w1 = w1 + al*1.0f;
        w2 = w2 + al*v2;
        a22 = a22 - (1.0f*w1 + w1*1.0f);
        a32 = a32 - (v2*w1 + w2*1.0f);
        a33 = a33 - (v2*w2 + w2*v2);
    }
    d[0] = a11; d[1] = a22; d[2] = a33;
    e[1] = a32;
    z[0][0] = 1.0f; z[0][1] = 0.0f; z[0][2] = 0.0f;
    z[1][0] = 0.0f; z[2][0] = 0.0f;
    z[1][1] = 1.0f - taui;
    z[1][2] = -taui * v2;
    z[2][1] = -taui * v2;
    z[2][2] = 1.0f - (taui * v2) * v2;
    ssteqr3(d, e, z);
}

// ---------------- stage 2: frames + tangent coords + bbox --------------------
__global__ __launch_bounds__(32) void frames_kernel(const float* __restrict__ pts) {
    int i = blockIdx.x * 32 + threadIdx.x;
    const int* idx = g_idx + i*KK;
    float mx = 0.f, my = 0.f, mz = 0.f;
    for (int r = 0; r < KK; r++) {
        int j = idx[r];
        mx += pts[3*j+0]; my += pts[3*j+1]; mz += pts[3*j+2];
    }
    mx /= 50.0f; my /= 50.0f; mz /= 50.0f;
    float A00=0.f, A01=0.f, A02=0.f, A11=0.f, A12=0.f, A22=0.f;
    for (int r = 0; r < KK; r++) {
        int j = idx[r];
        float cx = pts[3*j+0]-mx, cy = pts[3*j+1]-my, cz = pts[3*j+2]-mz;
        A00 += cx*cx; A01 += cx*cy; A02 += cx*cz;
        A11 += cy*cy; A12 += cy*cz; A22 += cz*cz;
    }
    A00*=0.5f; A01*=0.5f; A02*=0.5f; A11*=0.5f; A12*=0.5f; A22*=0.5f;

    float d[3];
    float V[3][3];
    ssyevd3(A00, A01, A02, A11, A12, A22, d, V);

    float nx  = V[0][0], ny  = V[1][0], nz  = V[2][0];
    float t1x = V[0][1], t1y = V[1][1], t1z = V[2][1];
    float t2x = V[0][2], t2y = V[1][2], t2z = V[2][2];
    float det = nx*(t1y*t2z - t1z*t2y)
              - ny*(t1x*t2z - t1z*t2x)
              + nz*(t1x*t2y - t1y*t2x);
    t1x *= det; t1y *= det; t1z *= det;
    g_nrm[3*i+0]=nx;  g_nrm[3*i+1]=ny;  g_nrm[3*i+2]=nz;
    g_t1 [3*i+0]=t1x; g_t1 [3*i+1]=t1y; g_t1 [3*i+2]=t1z;
    g_t2 [3*i+0]=t2x; g_t2 [3*i+1]=t2y; g_t2 [3*i+2]=t2z;
    float px = pts[3*i+0], py = pts[3*i+1], pz = pts[3*i+2];
    float bminx = INFINITY, bminy = INFINITY, bmaxx = -INFINITY, bmaxy = -INFINITY;
    for (int r = 0; r < KK; r++) {
        int j = idx[r];
        float dx = pts[3*j+0]-px, dy = pts[3*j+1]-py, dz = pts[3*j+2]-pz;
        float a0 = (dx*t1x + dy*t1y) + dz*t1z;
        float a1 = (dx*t2x + dy*t2y) + dz*t2z;
        g_dt[(i*KK+r)*2+0] = a0;
        g_dt[(i*KK+r)*2+1] = a1;
        bminx = fminf(bminx, a0); bmaxx = fmaxf(bmaxx, a0);
        bminy = fminf(bminy, a1); bmaxy = fmaxf(bmaxy, a1);
    }
    bminx *= 1.1f; bminy *= 1.1f; bmaxx *= 1.1f; bmaxy *= 1.1f;
    float ml = fmaxf(bmaxx - bminx, bmaxy - bminy);
    g_maxlen[i] = ml;
    for (int r = 0; r < KK; r++) {
        float a0 = g_dt[(i*KK+r)*2+0];
        float a1 = g_dt[(i*KK+r)*2+1];
        float c0 = (a0 - bminx)/ml*2.0f - 1.0f;
        float c1 = (a1 - bminy)/ml*2.0f - 1.0f;
        g_coords2[i*KK+r] = make_float2(c0, c1);
    }
}

// ---------------- stage 3: shape operator + gaussian curvature ---------------
__global__ __launch_bounds__(32) void gauss_kernel() {
    int i = blockIdx.x * 32 + threadIdx.x;
    const int* idx = g_idx + i*KK;
    float n0x = g_nrm[3*i+0], n0y = g_nrm[3*i+1], n0z = g_nrm[3*i+2];
    float t1x = g_t1[3*i+0],  t1y = g_t1[3*i+1],  t1z = g_t1[3*i+2];
    float t2x = g_t2[3*i+0],  t2y = g_t2[3*i+1],  t2z = g_t2[3*i+2];
    float xx=0.f, xy=0.f, yy=0.f;
    float y00=0.f, y01=0.f, y10=0.f, y11=0.f;
    for (int r = 0; r < KK; r++) {
        int j = idx[r];
        float lnx = g_nrm[3*j+0] - n0x;
        float lny = g_nrm[3*j+1] - n0y;
        float lnz = g_nrm[3*j+2] - n0z;
        float dn0 = (lnx*t1x + lny*t1y) + lnz*t1z;
        float dn1 = (lnx*t2x + lny*t2y) + lnz*t2z;
        float dt0 = g_dt[(i*KK+r)*2+0];
        float dt1 = g_dt[(i*KK+r)*2+1];
        xx += dt0*dt0; xy += dt0*dt1; yy += dt1*dt1;
        y00 += dn0*dt0; y01 += dn0*dt1;
        y10 += dn1*dt0; y11 += dn1*dt1;
    }
    float S00 = y00 + y00, S01 = y01 + y10, S11 = y11 + y11;
    float tr = xx + yy, df = xx - yy;
    float disc = sqrtf(df*df + 4.0f*xy*xy);
    float a = 0.5f*(tr - disc), b = 0.5f*(tr + disc);
    float vx = xy, vy = b - xx;
    float nn = sqrtf(vx*vx + vy*vy);
    if (nn > 0.0f) { vx /= nn; vy /= nn; }
    else           { vx = 1.0f; vy = 0.0f; }
    float q00 = vy, q10 = -vx, q01 = vx, q11 = vy;
    float sq00 = S00*q00 + S01*q10, sq01 = S00*q01 + S01*q11;
    float sq10 = S01*q00 + S11*q10, sq11 = S01*q01 + S11*q11;
    float m00 = q00*sq00 + q10*sq10;
    float m01 = q00*sq01 + q10*sq11;
    float m10 = q01*sq00 + q11*sq10;
    float m11 = q01*sq01 + q11*sq11;
    float E00 = m00 / (2.0f*a  + 1e-8f);
    float E01 = m01 / ((a + b) + 1e-8f);
    float E10 = m10 / ((a + b) + 1e-8f);
    float E11 = m11 / (2.0f*b  + 1e-8f);
    float u00 = q00*E00 + q01*E10, u01 = q00*E01 + q01*E11;
    float u10 = q10*E00 + q11*E10, u11 = q10*E01 + q11*E11;
    float w00 = u00*q00 + u01*q01;
    float w01 = u00*q10 + u01*q11;
    float w10 = u10*q00 + u11*q01;
    float w11 = u10*q10 + u11*q11;
    g_gauss[i] = w00*w11 - w01*w10;
}

// ---------------- stage 4: Voronoi cell count (argmin == 0) ------------------
// Regional-beater structure: per 8x8 tile, precompute the nearest site (j>=1)
// to the tile center; per cell test that site FIRST with the exact original
// distance comparison (settles ~98% of cells in one check), else fall back to
// the serial early-exit loop. 'lost' is an OR of exact predicates -> counts
// bit-identical to the passing kernels.
__global__ __launch_bounds__(128) void voronoi_kernel() {
    __shared__ float2 ss[KK];
    __shared__ int    sbeat[64];
    __shared__ int    part[128];
    int i = blockIdx.x;
    int t = threadIdx.x;
    if (t < KK) ss[t] = g_coords2[i*KK + t];
    __syncthreads();
    const float step = 2.0f / 63.0f;

    // per-tile nearest site (any j>=1), tile = 8x8 cells
    if (t < 64) {
        int ta = t >> 3, tb = t & 7;
        float cx = -1.0f + ((float)(ta*8) + 3.5f) * step;
        float cy = -1.0f + ((float)(tb*8) + 3.5f) * step;
        float bestd = INFINITY; int bestj = 1;
        for (int j = 1; j < KK; j++) {
            float ex = cx - ss[j].x, ey = cy - ss[j].y;
            float dj = ex*ex + ey*ey;
            if (dj < bestd) { bestd = dj; bestj = j; }
        }
        sbeat[t] = bestj;
    }
    __syncthreads();

    float s0x = ss[0].x, s0y = ss[0].y;
    int cnt = 0;
    for (int c = t; c < NG; c += 128) {
        int a = c >> 6, b = c & 63;
        float gx = -1.0f + (float)a * step;
        float gy = -1.0f + (float)b * step;
        float dx = gx - s0x, dy = gy - s0y;
        float d0 = dx*dx + dy*dy;
        int jstar = sbeat[(a >> 3)*8 + (b >> 3)];
        float2 sj = ss[jstar];
        float ex = gx - sj.x, ey = gy - sj.y;
        float djs = ex*ex + ey*ey;
        bool lost = djs < d0;
        if (!lost) {
            for (int j = 1; j < KK; j++) {
                float2 s = ss[j];
                float fx = gx - s.x, fy = gy - s.y;
                float dj = fx*fx + fy*fy;
                if (dj < d0) { lost = true; break; }
            }
        }
        cnt += lost ? 0 : 1;
    }
    part[t] = cnt;
    __syncthreads();
    for (int s = 64; s > 0; s >>= 1) {
        if (t < s) part[t] += part[t+s];
        __syncthreads();
    }
    if (t == 0) g_counts[i] = part[0];
}

// ---------------- stage 5: final reduction -----------------------------------
__global__ void final_kernel(float* __restrict__ out) {
    __shared__ double sh[256];
    int t = threadIdx.x;
    double acc = 0.0;
    for (int i = t; i < N; i += 256) {
        float ml = g_maxlen[i];
        float area = (float)g_counts[i] * (ml*ml) / 3969.0f;
        acc += (double)(g_gauss[i] * area);
    }
    sh[t] = acc;
    __syncthreads();
    for (int s = 128; s > 0; s >>= 1) {
        if (t < s) sh[t] += sh[t+s];
        __syncthreads();
    }
    if (t == 0) {
        float v = (float)sh[0];
        v = v / 2.0f;
        v = v / 3.14159274101257324f;
        out[0] = v;
    }
}

// ---------------- launch ------------------------------------------------------
extern "C" void kernel_launch(void* const* d_in, const int* in_sizes, int n_in,
                              void* d_out, int out_size) {
    const float* pts = (const float*)d_in[0];
    float* out = (float*)d_out;
    knn_q4_kernel<<<N/QB, TS>>>(pts);
    frames_kernel<<<N/32, 32>>>(pts);
    gauss_kernel <<<N/32, 32>>>();
    voronoi_kernel<<<N, 128>>>();
    final_kernel <<<1, 256>>>(out);
}